// round 8
// baseline (speedup 1.0000x reference)
#include <cuda_runtime.h>
#include <cuda_bf16.h>
#include <math.h>
#include <stdint.h>

// ---------------- problem constants ----------------
#define LLn   144
#define DIN   1024
#define DT    150
#define DTP   160
#define NOUT  4
#define BL    288
#define BZO   1152
#define OI    600
#define NFLAT 90000          // OI*DT      (flattened op1 N)
#define NF2   86400          // 576*DT     (flattened op2 N per batch)
#define NF3   82944          // 576*LLn    (flattened op3 N per batch)
#define OUT1N 23887872
#define LOGQ  -1.3862943611198906f

// ---------------- scratch (device globals, bf16 hi/lo splits) -------------
// pad columns [150,160) of g_w are never written -> stay zero (load-time
// zero-init), exactly what the K=160 consumers need.
__device__ __align__(256) __nv_bfloat16 g_xh[BL*DIN],        g_xl[BL*DIN];
__device__ __align__(256) __nv_bfloat16 g_Wph[4][DT*DIN],    g_Wpl[4][DT*DIN];   // [sel][n][k]
__device__ __align__(256) __nv_bfloat16 g_Wth[2][OI*DT*DTP], g_Wtl[2][OI*DT*DTP];// [tri][(oi,j)][k]
__device__ __align__(256) __nv_bfloat16 g_ph[4][BL*DTP],     g_pl[4][BL*DTP];
__device__ __align__(256) __nv_bfloat16 g_wh[(size_t)BZO*DT*DTP],  g_wl[(size_t)BZO*DT*DTP];
// g_t rows per batch: (z*144+y)*4+o  (o innermost -> softmax quads adjacent)
__device__ __align__(256) __nv_bfloat16 g_th[(size_t)BZO*LLn*DTP], g_tl[(size_t)BZO*LLn*DTP];

// ---------------- helpers ----------------
__device__ __forceinline__ void split2(float v, __nv_bfloat16& h, __nv_bfloat16& l) {
    h = __float2bfloat16_rn(v);
    l = __float2bfloat16_rn(v - __bfloat162float(h));
}
__device__ __forceinline__ void store_pair(__nv_bfloat16* baseH, __nv_bfloat16* baseL,
                                           size_t d, float v0, float v1) {
    __nv_bfloat16 h0, l0, h1, l1;
    split2(v0, h0, l0);
    split2(v1, h1, l1);
    uint32_t ph = (uint32_t)__bfloat16_as_ushort(h0) | ((uint32_t)__bfloat16_as_ushort(h1) << 16);
    uint32_t pl = (uint32_t)__bfloat16_as_ushort(l0) | ((uint32_t)__bfloat16_as_ushort(l1) << 16);
    *(uint32_t*)(baseH + d) = ph;
    *(uint32_t*)(baseL + d) = pl;
}
__device__ __forceinline__ uint32_t smem_u32(const void* p) {
    uint32_t a;
    asm("{ .reg .u64 t; cvta.to.shared.u64 t, %1; cvt.u32.u64 %0, t; }" : "=r"(a) : "l"(p));
    return a;
}
__device__ __forceinline__ void ldm4(uint32_t* d, uint32_t addr) {
    asm volatile("ldmatrix.sync.aligned.m8n8.x4.shared.b16 {%0,%1,%2,%3}, [%4];"
        : "=r"(d[0]), "=r"(d[1]), "=r"(d[2]), "=r"(d[3]) : "r"(addr));
}
__device__ __forceinline__ void mma_bf16(float* c, const uint32_t* a, uint32_t b0, uint32_t b1) {
    asm volatile("mma.sync.aligned.m16n8k16.row.col.f32.bf16.bf16.f32 "
        "{%0,%1,%2,%3}, {%4,%5,%6,%7}, {%8,%9}, {%0,%1,%2,%3};"
        : "+f"(c[0]), "+f"(c[1]), "+f"(c[2]), "+f"(c[3])
        : "r"(a[0]), "r"(a[1]), "r"(a[2]), "r"(a[3]), "r"(b0), "r"(b1));
}
__device__ __forceinline__ void cpa16(uint32_t dst, const void* src, uint32_t sz) {
    asm volatile("cp.async.cg.shared.global [%0], [%1], 16, %2;"
        :: "r"(dst), "l"(src), "r"(sz) : "memory");
}
__device__ __forceinline__ float4 lsm4(float a, float b, float c, float d) {
    float m = fmaxf(fmaxf(a, b), fmaxf(c, d));
    float s = expf(a - m) + expf(b - m) + expf(c - m) + expf(d - m);
    float l = m + logf(s);
    return make_float4(a - l, b - l, c - l, d - l);
}

// ---------------- prep kernels ----------------
__global__ void prep_x(const float* __restrict__ x) {
    int i = blockIdx.x * 256 + threadIdx.x;
    if (i >= BL * DIN) return;
    split2(x[i], g_xh[i], g_xl[i]);
}
__global__ void prep_pw4(const float* __restrict__ W0, const float* __restrict__ W1,
                         const float* __restrict__ W2, const float* __restrict__ W3) {
    int i = blockIdx.x * 256 + threadIdx.x;
    if (i >= DT * DIN) return;
    int sel = blockIdx.y;
    const float* W = (sel == 0) ? W0 : (sel == 1) ? W1 : (sel == 2) ? W2 : W3;
    int n = i >> 10, k = i & 1023;
    split2(__ldg(&W[k * DT + n]), g_Wph[sel][i], g_Wpl[sel][i]);
}
__global__ void prep_wt2(const float* __restrict__ Wa, const float* __restrict__ Wb) {
    __shared__ float t[32][33];
    int oi = blockIdx.x;
    int tri = blockIdx.z;
    const float* W = tri ? Wb : Wa;
    int kt = (blockIdx.y / 5) * 32, jt = (blockIdx.y % 5) * 32;
    int tx = threadIdx.x, ty = threadIdx.y;
    int k = kt + ty, j = jt + tx;
    float v = (k < DT && j < DT) ? W[(size_t)oi * (DT * DT) + k * DT + j] : 0.f;
    t[ty][tx] = v;
    __syncthreads();
    int j2 = jt + ty, k2 = kt + tx;
    if (j2 < DT && k2 < DTP) {
        float u = t[tx][ty];
        size_t d = (size_t)oi * (DT * DTP) + (size_t)j2 * DTP + k2;
        split2(u, g_Wth[tri][d], g_Wtl[tri][d]);
    }
}

// ---------------- HMMA GEMM: BM=48*MF, BN=96, BK=16, 192 thr, dbl-buffered -
// Per-warp: 16*MF m-rows x 48 n-cols = MF x 6 quads. pitch-48B smem rows.
// MODE 0 (MF=1): proj  x(288x1024) @ Wp[z]          -> g_p[z]
// MODE 1 (MF=3): op1   sh(288xDTP) @ Wt[tri] N=90000 -> g_w
// MODE 2 (MF=3): op2   Y_b(144xDTP) @ g_w[b] N=86400 -> g_t (o-innermost)
// MODE 3 (MF=3): op3/1 X_b(144xDTP) @ g_t[b] N=82944 -> out, fused logsoftmax
// MODE 4 (MF=3): op3/2 same, transposed final coords
template<int MODE, int MF>
__global__ __launch_bounds__(192)
void tk(const float* __restrict__ b0s, const float* __restrict__ b1s,
        const float* __restrict__ b2s, const float* __restrict__ b3s,
        float* __restrict__ outp, int sel, int tri)
{
    constexpr int BMR   = 48 * MF;
    constexpr int OFFAL = BMR * 48;
    constexpr int OFFBH = 2 * OFFAL;
    constexpr int OFFBL = OFFBH + 4608;
    constexpr int STGc  = OFFBH + 9216;
    constexpr int NITc  = MF + 2;           // (192*MF + 384)/192

    __shared__ __align__(16) char sm[2][STGc];

    const int tid  = threadIdx.x;
    const int lane = tid & 31, warp = tid >> 5;
    const int wm = warp >> 1, wn = warp & 1;
    const int bx = blockIdx.x, by = blockIdx.y, zb = blockIdx.z;
    const int m0 = bx * BMR, n0 = by * 96;

    // ---- MODE4: fully-masked block -> fill constants, skip GEMM ----
    if constexpr (MODE == 4) {
        bool allmask = true;
        #pragma unroll 1
        for (int qd = 0; qd < 24; qd++) {
            int nq = (n0 >> 2) + qd;
            if (nq / LLn <= nq % LLn) { allmask = false; break; }
        }
        if (allmask) {
            const float4 c4 = make_float4(LOGQ, LOGQ, LOGQ, LOGQ);
            for (int idx = tid; idx < BMR * 24; idx += 192) {
                int mm = m0 + idx / 24;
                int nq = (n0 >> 2) + idx % 24;
                int z = nq / LLn, t = nq % LLn;
                ((float4*)outp)[(((size_t)(zb * LLn + z) * LLn + t) * LLn + mm)] = c4;
            }
            return;
        }
    }

    const __nv_bfloat16 *Ah, *Al, *Bh, *Bl;
    int pitchA, pitchB, KT, NB;
    if constexpr (MODE == 0) {
        Ah = g_xh; Al = g_xl; Bh = g_Wph[zb]; Bl = g_Wpl[zb];
        pitchA = DIN; pitchB = DIN; KT = 64; NB = DT;
    }
    if constexpr (MODE == 1) {
        Ah = g_ph[0]; Al = g_pl[0]; Bh = g_Wth[tri]; Bl = g_Wtl[tri];
        pitchA = DTP; pitchB = DTP; KT = 10; NB = NFLAT;
    }
    if constexpr (MODE == 2) {
        Ah = g_ph[sel] + (size_t)zb * LLn * DTP; Al = g_pl[sel] + (size_t)zb * LLn * DTP;
        Bh = g_wh + (size_t)zb * 576 * DT * DTP; Bl = g_wl + (size_t)zb * 576 * DT * DTP;
        pitchA = DTP; pitchB = DTP; KT = 10; NB = NF2;
    }
    if constexpr (MODE >= 3) {
        Ah = g_ph[sel] + (size_t)zb * LLn * DTP; Al = g_pl[sel] + (size_t)zb * LLn * DTP;
        Bh = g_th + (size_t)zb * NF3 * DTP;      Bl = g_tl + (size_t)zb * NF3 * DTP;
        pitchA = DTP; pitchB = DTP; KT = 10; NB = NF3;
    }

    const uint32_t sbase = smem_u32(sm);

    // ---- per-thread staging plan: NITc 16B segments per chunk ----
    const __nv_bfloat16* sptr[NITc];
    uint32_t sdst[NITc], ssz[NITc];
    #pragma unroll
    for (int it = 0; it < NITc; it++) {
        int idx = tid + it * 192;
        if (idx < 192 * MF) {                         // A: rows BMR, 2 segs, hi/lo
            int mat = idx / (96 * MF);
            int rem = idx - mat * (96 * MF);
            int row = rem >> 1, seg = rem & 1;
            sptr[it] = (mat ? Al : Ah) + (size_t)(m0 + row) * pitchA + seg * 8;
            sdst[it] = (uint32_t)(mat * OFFAL + row * 48 + seg * 16);
            ssz[it]  = 16;
        } else {                                      // B: 96 rows, 2 segs, hi/lo
            int idxB = idx - 192 * MF;
            int mat = idxB / 192;
            int rem = idxB - mat * 192;
            int row = rem >> 1, seg = rem & 1;
            int gr = n0 + row;
            bool vv = gr < NB;
            sptr[it] = (mat ? Bl : Bh) + (size_t)(vv ? gr : n0) * pitchB + seg * 8;
            sdst[it] = (uint32_t)(OFFBH + mat * 4608 + row * 48 + seg * 16);
            ssz[it]  = vv ? 16u : 0u;
        }
    }

    // ---- ldmatrix lane offsets (pitch-48 rows, conflict-free) ----
    const int q = lane >> 3, r = lane & 7;
    const uint32_t aOff  = (uint32_t)((wm * 16 * MF + ((q & 1) ? 8 : 0) + r) * 48 + ((q >> 1) ? 16 : 0));
    const uint32_t bOff0 = (uint32_t)((wn * 48 + ((lane >> 4) ? 8 : 0) + r) * 48 + ((q & 1) ? 16 : 0));

    // MODE3: warp-level compute skip when this warp's m-range is fully masked
    bool wskip = false;
    if constexpr (MODE == 3)
        wskip = ((n0 >> 2) / LLn) > (wm * 16 * MF + 16 * MF - 1);

    float acc[MF][6][4];
    #pragma unroll
    for (int f = 0; f < MF; f++)
        #pragma unroll
        for (int i = 0; i < 6; i++)
            #pragma unroll
            for (int j = 0; j < 4; j++) acc[f][i][j] = 0.f;

    auto stageCh = [&](int buf) {
        const uint32_t sb = sbase + (uint32_t)(buf * STGc);
        #pragma unroll
        for (int it = 0; it < NITc; it++) {
            cpa16(sb + sdst[it], sptr[it], ssz[it]);
            sptr[it] += 16;
        }
        asm volatile("cp.async.commit_group;" ::: "memory");
    };

    stageCh(0);

    for (int ch = 0; ch < KT; ch++) {
        if (ch + 1 < KT) {
            stageCh((ch + 1) & 1);
            asm volatile("cp.async.wait_group 1;" ::: "memory");
        } else {
            asm volatile("cp.async.wait_group 0;" ::: "memory");
        }
        __syncthreads();

        if (!wskip) {
            const uint32_t cb = sbase + (uint32_t)((ch & 1) * STGc);
            uint32_t ah[MF][4], al4[MF][4];
            #pragma unroll
            for (int f = 0; f < MF; f++) {
                ldm4(ah[f],  cb + aOff + (uint32_t)(f * 768));
                ldm4(al4[f], cb + OFFAL + aOff + (uint32_t)(f * 768));
            }
            #pragma unroll
            for (int g = 0; g < 3; g++) {
                uint32_t bh[4], bl[4];
                const uint32_t bo = bOff0 + (uint32_t)(g * 768);
                ldm4(bh, cb + OFFBH + bo);
                ldm4(bl, cb + OFFBL + bo);
                #pragma unroll
                for (int f = 0; f < MF; f++) {
                    mma_bf16(acc[f][2 * g],     ah[f],  bh[0], bh[1]);
                    mma_bf16(acc[f][2 * g],     ah[f],  bl[0], bl[1]);
                    mma_bf16(acc[f][2 * g],     al4[f], bh[0], bh[1]);
                    mma_bf16(acc[f][2 * g + 1], ah[f],  bh[2], bh[3]);
                    mma_bf16(acc[f][2 * g + 1], ah[f],  bl[2], bl[3]);
                    mma_bf16(acc[f][2 * g + 1], al4[f], bh[2], bh[3]);
                }
            }
        }
        __syncthreads();
    }

    // ---- store ----
    const float* bias = nullptr;
    if constexpr (MODE == 0)
        bias = (zb == 0) ? b0s : (zb == 1) ? b1s : (zb == 2) ? b2s : b3s;

    const int g8 = lane >> 2, cc = lane & 3, t2 = cc * 2;
    const int nbb = n0 + wn * 48;

    #pragma unroll
    for (int f = 0; f < MF; f++) {
        const int mbF = m0 + wm * 16 * MF + f * 16;
        if constexpr (MODE <= 2) {
            #pragma unroll
            for (int j = 0; j < 6; j++) {
                #pragma unroll
                for (int h = 0; h < 2; h++) {
                    const int m = mbF + g8 + h * 8;
                    const int n = nbb + j * 8 + t2;          // even
                    const float v0 = acc[f][j][2 * h], v1 = acc[f][j][2 * h + 1];
                    if constexpr (MODE == 0) {
                        if (n + 1 < DTP) {
                            float a0 = (n < DT) ? v0 + bias[n] : 0.f;
                            float a1 = (n + 1 < DT) ? v1 + bias[n + 1] : 0.f;
                            store_pair(g_ph[zb], g_pl[zb], (size_t)m * DTP + n, a0, a1);
                        }
                    }
                    if constexpr (MODE == 1) {
                        if (n < NFLAT) {
                            int oi = n / DT, jj = n - oi * DT;
                            int o = oi / DT, i = oi - o * DT;
                            size_t d = ((size_t)(m * NOUT + o) * DT + i) * DTP + jj;
                            store_pair(g_wh, g_wl, d, v0, v1);
                        }
                    }
                    if constexpr (MODE == 2) {
                        int qq = n / DT, i = n - qq * DT;
                        int z = qq >> 2, o = qq & 3;
                        size_t rrow = ((size_t)(z * LLn + m)) * NOUT + o;
                        size_t d = ((size_t)zb * NF3 + rrow) * DTP + i;
                        store_pair(g_th, g_tl, d, v0, v1);
                    }
                }
            }
        } else {
            // fused mask + log_softmax; one float4 per quad, even-cc lanes store
            #pragma unroll
            for (int j = 0; j < 6; j++) {
                #pragma unroll
                for (int h = 0; h < 2; h++) {
                    const float a0 = acc[f][j][2 * h], a1 = acc[f][j][2 * h + 1];
                    const float p0 = __shfl_xor_sync(0xffffffffu, a0, 1);
                    const float p1 = __shfl_xor_sync(0xffffffffu, a1, 1);
                    if (!(cc & 1)) {
                        const int nq = (nbb + j * 8 + ((cc == 2) ? 4 : 0)) >> 2;
                        const int z = nq / LLn, t = nq - z * LLn;
                        const int m = mbF + g8 + h * 8;
                        const bool keep = (MODE == 3) ? (z <= m) : (z <= t);
                        float4 r4;
                        if (keep) r4 = lsm4(a0, a1, p0, p1);
                        else      r4 = make_float4(LOGQ, LOGQ, LOGQ, LOGQ);
                        size_t qb;
                        if constexpr (MODE == 3)
                            qb = (((size_t)(zb * LLn + z) * LLn + m) * LLn + t);
                        else
                            qb = (((size_t)(zb * LLn + z) * LLn + t) * LLn + m);
                        ((float4*)outp)[qb] = r4;
                    }
                }
            }
        }
    }
}

// ---------------------------------------------------------------------------
extern "C" void kernel_launch(void* const* d_in, const int* in_sizes, int n_in,
                              void* d_out, int out_size)
{
    const float* x     = (const float*)d_in[0];
    const float* W_sh  = (const float*)d_in[1];
    const float* b_sh  = (const float*)d_in[2];
    const float* W_st  = (const float*)d_in[3];
    const float* b_st  = (const float*)d_in[4];
    const float* W_oh  = (const float*)d_in[5];
    const float* b_oh  = (const float*)d_in[6];
    const float* W_ot  = (const float*)d_in[7];
    const float* b_ot  = (const float*)d_in[8];
    const float* W_t1  = (const float*)d_in[9];
    const float* W_t2  = (const float*)d_in[10];
    float* out = (float*)d_out;

    // prep: split inputs/weights into bf16 hi/lo
    prep_x<<<(BL * DIN + 255) / 256, 256>>>(x);
    prep_pw4<<<dim3((DT * DIN + 255) / 256, 4), 256>>>(W_sh, W_st, W_oh, W_ot);
    prep_wt2<<<dim3(OI, 25, 2), dim3(32, 32)>>>(W_t1, W_t2);

    // projections: M=288 (6x48) x N 2 tiles x 4 sel
    tk<0, 1><<<dim3(6, 2, 4), 192>>>(b_sh, b_st, b_oh, b_ot, nullptr, 0, 0);

    // triaffine 1: (x=st[1], y=oh[2], z=sh[0], W1)
    tk<1, 3><<<dim3(2, 938, 1), 192>>>(nullptr, nullptr, nullptr, nullptr, nullptr, 0, 0);
    tk<2, 3><<<dim3(1, 900, 2), 192>>>(nullptr, nullptr, nullptr, nullptr, nullptr, 2, 0);
    tk<3, 3><<<dim3(1, 864, 2), 192>>>(nullptr, nullptr, nullptr, nullptr, out, 1, 0);

    // triaffine 2: (x=ot[3], y=st[1], z=sh[0], W2), transposed final coords
    tk<1, 3><<<dim3(2, 938, 1), 192>>>(nullptr, nullptr, nullptr, nullptr, nullptr, 0, 1);
    tk<2, 3><<<dim3(1, 900, 2), 192>>>(nullptr, nullptr, nullptr, nullptr, nullptr, 1, 0);
    tk<4, 3><<<dim3(1, 864, 2), 192>>>(nullptr, nullptr, nullptr, nullptr, out + OUT1N, 3, 0);
}

// round 12
// speedup vs baseline: 1.0409x; 1.0409x over previous
#include <cuda_runtime.h>
#include <cuda_bf16.h>
#include <math.h>
#include <stdint.h>

// ---------------- problem constants ----------------
#define LLn   144
#define DIN   1024
#define DT    150
#define DTP   160
#define NOUT  4
#define BL    288
#define BZO   1152
#define OI    600
#define NFLAT 90000          // OI*DT      (flattened op1 N)
#define NF2   86400          // 576*DT     (flattened op2 N per batch)
#define NF3   82944          // 576*LLn    (flattened op3 N per batch)
#define OUT1N 23887872
#define LOGQ  -1.3862943611198906f

// ---------------- scratch (device globals, bf16 hi/lo splits) -------------
__device__ __align__(256) __nv_bfloat16 g_xh[BL*DIN],        g_xl[BL*DIN];
__device__ __align__(256) __nv_bfloat16 g_Wph[4][DT*DIN],    g_Wpl[4][DT*DIN];   // [sel][n][k]
__device__ __align__(256) __nv_bfloat16 g_Wth[2][OI*DT*DTP], g_Wtl[2][OI*DT*DTP];// [tri][(oi,j)][k]
__device__ __align__(256) __nv_bfloat16 g_ph[4][BL*DTP],     g_pl[4][BL*DTP];
__device__ __align__(256) __nv_bfloat16 g_wh[(size_t)BZO*DT*DTP],  g_wl[(size_t)BZO*DT*DTP];
// g_t rows per batch: (z*144+y)*4+o  (o innermost -> softmax quads adjacent)
__device__ __align__(256) __nv_bfloat16 g_th[(size_t)BZO*LLn*DTP], g_tl[(size_t)BZO*LLn*DTP];

// ---------------- helpers ----------------
__device__ __forceinline__ void split2(float v, __nv_bfloat16& h, __nv_bfloat16& l) {
    h = __float2bfloat16_rn(v);
    l = __float2bfloat16_rn(v - __bfloat162float(h));
}
__device__ __forceinline__ void store_pair(__nv_bfloat16* baseH, __nv_bfloat16* baseL,
                                           size_t d, float v0, float v1) {
    __nv_bfloat16 h0, l0, h1, l1;
    split2(v0, h0, l0);
    split2(v1, h1, l1);
    uint32_t ph = (uint32_t)__bfloat16_as_ushort(h0) | ((uint32_t)__bfloat16_as_ushort(h1) << 16);
    uint32_t pl = (uint32_t)__bfloat16_as_ushort(l0) | ((uint32_t)__bfloat16_as_ushort(l1) << 16);
    *(uint32_t*)(baseH + d) = ph;
    *(uint32_t*)(baseL + d) = pl;
}
__device__ __forceinline__ uint32_t smem_u32(const void* p) {
    uint32_t a;
    asm("{ .reg .u64 t; cvta.to.shared.u64 t, %1; cvt.u32.u64 %0, t; }" : "=r"(a) : "l"(p));
    return a;
}
__device__ __forceinline__ void ldm4(uint32_t* d, uint32_t addr) {
    asm volatile("ldmatrix.sync.aligned.m8n8.x4.shared.b16 {%0,%1,%2,%3}, [%4];"
        : "=r"(d[0]), "=r"(d[1]), "=r"(d[2]), "=r"(d[3]) : "r"(addr));
}
__device__ __forceinline__ void mma_bf16(float* c, const uint32_t* a, uint32_t b0, uint32_t b1) {
    asm volatile("mma.sync.aligned.m16n8k16.row.col.f32.bf16.bf16.f32 "
        "{%0,%1,%2,%3}, {%4,%5,%6,%7}, {%8,%9}, {%0,%1,%2,%3};"
        : "+f"(c[0]), "+f"(c[1]), "+f"(c[2]), "+f"(c[3])
        : "r"(a[0]), "r"(a[1]), "r"(a[2]), "r"(a[3]), "r"(b0), "r"(b1));
}
__device__ __forceinline__ void cpa16(uint32_t dst, const void* src, uint32_t sz) {
    asm volatile("cp.async.cg.shared.global [%0], [%1], 16, %2;"
        :: "r"(dst), "l"(src), "r"(sz) : "memory");
}
__device__ __forceinline__ float4 lsm4(float a, float b, float c, float d) {
    float m = fmaxf(fmaxf(a, b), fmaxf(c, d));
    float s = expf(a - m) + expf(b - m) + expf(c - m) + expf(d - m);
    float l = m + logf(s);
    return make_float4(a - l, b - l, c - l, d - l);
}

// ---------------- prep kernels ----------------
__global__ void prep_x(const float* __restrict__ x) {
    int i = blockIdx.x * 256 + threadIdx.x;
    if (i >= BL * DIN) return;
    split2(x[i], g_xh[i], g_xl[i]);
}
__global__ void prep_pw4(const float* __restrict__ W0, const float* __restrict__ W1,
                         const float* __restrict__ W2, const float* __restrict__ W3) {
    int i = blockIdx.x * 256 + threadIdx.x;
    if (i >= DT * DIN) return;
    int sel = blockIdx.y;
    const float* W = (sel == 0) ? W0 : (sel == 1) ? W1 : (sel == 2) ? W2 : W3;
    int n = i >> 10, k = i & 1023;
    split2(__ldg(&W[k * DT + n]), g_Wph[sel][i], g_Wpl[sel][i]);
}
__global__ void prep_wt2(const float* __restrict__ Wa, const float* __restrict__ Wb) {
    __shared__ float t[32][33];
    int oi = blockIdx.x;
    int tri = blockIdx.z;
    const float* W = tri ? Wb : Wa;
    int kt = (blockIdx.y / 5) * 32, jt = (blockIdx.y % 5) * 32;
    int tx = threadIdx.x, ty = threadIdx.y;
    int k = kt + ty, j = jt + tx;
    float v = (k < DT && j < DT) ? W[(size_t)oi * (DT * DT) + k * DT + j] : 0.f;
    t[ty][tx] = v;
    __syncthreads();
    int j2 = jt + ty, k2 = kt + tx;
    if (j2 < DT && k2 < DTP) {
        float u = t[tx][ty];
        size_t d = (size_t)oi * (DT * DTP) + (size_t)j2 * DTP + k2;
        split2(u, g_Wth[tri][d], g_Wtl[tri][d]);
    }
}

// ---------------- HMMA GEMM: BM=48, BN=128, BK=32, 192 thr, dbl-buffered ---
// smem/stage: Ah[48x80B] Al Bh[128x80B] Bl = 28160B; 2 stages + 2KB scratch.
// Warp grid 3(m) x 2(n): each warp 16m x 64n = 8 acc quads.
// MODE 0: proj   x(288x1024) @ Wp[z](as [n][k]) -> g_p[z]   (z=blockIdx.z)
// MODE 1: op1    sh(288xDTP) @ Wt[tri] flat N=90000 -> g_w
// MODE 2: op2    Y_b(144xDTP) @ g_w[b] flat N=86400 -> g_t (o-innermost rows)
// MODE 3: op3/1  X_b(144xDTP) @ g_t[b] flat N=82944 -> out, fused logsoftmax
// MODE 4: op3/2  same, transposed final coords, fused logsoftmax
#define STG    28160
#define OFF_AL 3840
#define OFF_BH 7680
#define OFF_BL 17920
#define DUMMY  56320         // 2KB scratch for idle staging slots (absolute)
#define SMTOT  58368
#define NIT    8             // ceil(1408 / 192)

template<int MODE>
__global__ __launch_bounds__(192)
void tk(const float* __restrict__ b0s, const float* __restrict__ b1s,
        const float* __restrict__ b2s, const float* __restrict__ b3s,
        float* __restrict__ outp, int sel, int tri)
{
    extern __shared__ __align__(16) char sm[];

    const int tid  = threadIdx.x;
    const int lane = tid & 31, warp = tid >> 5;
    const int wm = warp >> 1, wn = warp & 1;
    const int bx = blockIdx.x, by = blockIdx.y, zb = blockIdx.z;
    const int m0 = bx * 48, n0 = by * 128;

    // ---- fully-masked block: fill constants, skip GEMM ----
    if constexpr (MODE == 3 || MODE == 4) {
        bool allmask;
        if constexpr (MODE == 3) {
            allmask = ((n0 >> 2) / LLn) > (m0 + 47);
        } else {
            allmask = true;
            #pragma unroll 1
            for (int qd = 0; qd < 32; qd++) {
                int nq = (n0 >> 2) + qd;
                if (nq / LLn <= nq % LLn) { allmask = false; break; }
            }
        }
        if (allmask) {
            const float4 c4 = make_float4(LOGQ, LOGQ, LOGQ, LOGQ);
            for (int idx = tid; idx < 48 * 32; idx += 192) {
                int mm = m0 + idx / 32;
                int nq = (n0 >> 2) + idx % 32;
                int z = nq / LLn, t = nq % LLn;
                size_t qb;
                if constexpr (MODE == 3)
                    qb = (((size_t)(zb * LLn + z) * LLn + mm) * LLn + t);
                else
                    qb = (((size_t)(zb * LLn + z) * LLn + t) * LLn + mm);
                ((float4*)outp)[qb] = c4;
            }
            return;
        }
    }

    const __nv_bfloat16 *Ah, *Al, *Bh, *Bl;
    int pitchA, pitchB, KT, NB;
    if constexpr (MODE == 0) {
        Ah = g_xh; Al = g_xl; Bh = g_Wph[zb]; Bl = g_Wpl[zb];
        pitchA = DIN; pitchB = DIN; KT = 32; NB = DT;
    }
    if constexpr (MODE == 1) {
        Ah = g_ph[0]; Al = g_pl[0]; Bh = g_Wth[tri]; Bl = g_Wtl[tri];
        pitchA = DTP; pitchB = DTP; KT = 5; NB = NFLAT;
    }
    if constexpr (MODE == 2) {
        Ah = g_ph[sel] + (size_t)zb * LLn * DTP; Al = g_pl[sel] + (size_t)zb * LLn * DTP;
        Bh = g_wh + (size_t)zb * 576 * DT * DTP; Bl = g_wl + (size_t)zb * 576 * DT * DTP;
        pitchA = DTP; pitchB = DTP; KT = 5; NB = NF2;
    }
    if constexpr (MODE >= 3) {
        Ah = g_ph[sel] + (size_t)zb * LLn * DTP; Al = g_pl[sel] + (size_t)zb * LLn * DTP;
        Bh = g_th + (size_t)zb * NF3 * DTP;      Bl = g_tl + (size_t)zb * NF3 * DTP;
        pitchA = DTP; pitchB = DTP; KT = 5; NB = NF3;
    }

    const uint32_t sbase = smem_u32(sm);

    // ---- per-thread staging plan: NIT 16B segments (1408 real + idle) ----
    // sabs[it]=1 -> dst is absolute (scratch, both buffers); else stage-relative.
    const __nv_bfloat16* sptr[NIT];
    uint32_t sdst[NIT], ssz[NIT], sabs[NIT];
    #pragma unroll
    for (int it = 0; it < NIT; it++) {
        int idx = tid + it * 192;                    // 0..1535
        if (idx < 384) {                             // A: Ah then Al
            int mat = idx / 192;
            int rem = idx - mat * 192;
            int row = rem >> 2, seg = rem & 3;
            sptr[it] = (mat ? Al : Ah) + (size_t)(m0 + row) * pitchA + seg * 8;
            sdst[it] = (uint32_t)(mat * OFF_AL + row * 80 + seg * 16);
            ssz[it]  = 16;
            sabs[it] = 0;
        } else if (idx < 1408) {                     // B: Bh then Bl, 128 rows
            int idxB = idx - 384;                    // 0..1023
            int mat = idxB >> 9;                     // 0=Bh 1=Bl
            int brem = idxB & 511;
            int row = brem >> 2, seg = brem & 3;
            int gr = n0 + row;
            bool vv = gr < NB;
            sptr[it] = (mat ? Bl : Bh) + (size_t)(vv ? gr : n0) * pitchB + seg * 8;
            sdst[it] = (uint32_t)(OFF_BH + mat * 10240 + row * 80 + seg * 16);
            ssz[it]  = vv ? 16u : 0u;
            sabs[it] = 0;
        } else {                                     // idle -> absolute scratch
            sptr[it] = Ah;
            sdst[it] = (uint32_t)(DUMMY + (tid & 127) * 16);
            ssz[it]  = 0;
            sabs[it] = 1;
        }
    }

    // ---- ldmatrix lane offsets (pitch-80 rows, conflict-free) ----
    const int q = lane >> 3, r = lane & 7;
    const uint32_t aOff  = (uint32_t)((wm * 16 + ((q & 1) ? 8 : 0) + r) * 80 + ((q >> 1) ? 16 : 0));
    const uint32_t bOff0 = (uint32_t)((wn * 64 + ((lane >> 4) ? 8 : 0) + r) * 80 + ((q & 1) ? 16 : 0));

    // MODE3: warp-level compute skip when this warp's m-range is fully masked
    bool wskip = false;
    if constexpr (MODE == 3)
        wskip = ((n0 >> 2) / LLn) > (m0 + wm * 16 + 15);

    float acc[8][4];
    #pragma unroll
    for (int i = 0; i < 8; i++)
        #pragma unroll
        for (int j = 0; j < 4; j++) acc[i][j] = 0.f;

    auto stageCh = [&](int buf) {
        const uint32_t sb = sbase + (uint32_t)(buf * STG);
        #pragma unroll
        for (int it = 0; it < NIT; it++) {
            cpa16((sabs[it] ? sbase : sb) + sdst[it], sptr[it], ssz[it]);
            sptr[it] += 32;
        }
        asm volatile("cp.async.commit_group;" ::: "memory");
    };

    stageCh(0);

    for (int ch = 0; ch < KT; ch++) {
        if (ch + 1 < KT) {
            stageCh((ch + 1) & 1);
            asm volatile("cp.async.wait_group 1;" ::: "memory");
        } else {
            asm volatile("cp.async.wait_group 0;" ::: "memory");
        }
        __syncthreads();

        if (!wskip) {
            const uint32_t cb = sbase + (uint32_t)((ch & 1) * STG);
            #pragma unroll
            for (int ks = 0; ks < 2; ks++) {
                const uint32_t ko = (uint32_t)(ks * 32);
                uint32_t ah[4], al4[4];
                ldm4(ah,  cb + aOff + ko);
                ldm4(al4, cb + OFF_AL + aOff + ko);
                #pragma unroll
                for (int g = 0; g < 4; g++) {
                    uint32_t bh[4], bl[4];
                    const uint32_t bo = bOff0 + (uint32_t)(g * 1280) + ko;
                    ldm4(bh, cb + OFF_BH + bo);
                    ldm4(bl, cb + OFF_BL + bo);
                    mma_bf16(acc[2 * g],     ah,  bh[0], bh[1]);
                    mma_bf16(acc[2 * g],     ah,  bl[0], bl[1]);
                    mma_bf16(acc[2 * g],     al4, bh[0], bh[1]);
                    mma_bf16(acc[2 * g + 1], ah,  bh[2], bh[3]);
                    mma_bf16(acc[2 * g + 1], ah,  bl[2], bl[3]);
                    mma_bf16(acc[2 * g + 1], al4, bh[2], bh[3]);
                }
            }
        }
        __syncthreads();
    }

    // ---- store ----
    const float* bias = nullptr;
    if constexpr (MODE == 0)
        bias = (zb == 0) ? b0s : (zb == 1) ? b1s : (zb == 2) ? b2s : b3s;

    const int g8 = lane >> 2, cc = lane & 3, t2 = cc * 2;
    const int mb = m0 + wm * 16, nbb = n0 + wn * 64;

    if constexpr (MODE <= 2) {
        // pair-packed bf16 stores (even n; rows even-width so pairs never straddle)
        #pragma unroll
        for (int j = 0; j < 8; j++) {
            #pragma unroll
            for (int h = 0; h < 2; h++) {
                const int m = mb + g8 + h * 8;
                const int n = nbb + j * 8 + t2;          // even
                const float v0 = acc[j][2 * h], v1 = acc[j][2 * h + 1];
                if constexpr (MODE == 0) {
                    if (n + 1 < DTP) {
                        float a0 = (n < DT) ? v0 + bias[n] : 0.f;
                        float a1 = (n + 1 < DT) ? v1 + bias[n + 1] : 0.f;
                        store_pair(g_ph[zb], g_pl[zb], (size_t)m * DTP + n, a0, a1);
                    }
                }
                if constexpr (MODE == 1) {
                    if (n < NFLAT) {
                        int oi = n / DT, jj = n - oi * DT;
                        int o = oi / DT, i = oi - o * DT;
                        size_t d = ((size_t)(m * NOUT + o) * DT + i) * DTP + jj;
                        store_pair(g_wh, g_wl, d, v0, v1);
                    }
                }
                if constexpr (MODE == 2) {
                    int qq = n / DT, i = n - qq * DT;
                    int z = qq >> 2, o = qq & 3;
                    size_t rrow = ((size_t)(z * LLn + m)) * NOUT + o;
                    size_t d = ((size_t)zb * NF3 + rrow) * DTP + i;
                    store_pair(g_th, g_tl, d, v0, v1);
                }
            }
        }
    } else {
        // fused mask + log_softmax; one float4 per quad, even-cc lanes store
        #pragma unroll
        for (int j = 0; j < 8; j++) {
            #pragma unroll
            for (int h = 0; h < 2; h++) {
                const float a0 = acc[j][2 * h], a1 = acc[j][2 * h + 1];
                const float p0 = __shfl_xor_sync(0xffffffffu, a0, 1);
                const float p1 = __shfl_xor_sync(0xffffffffu, a1, 1);
                if (!(cc & 1)) {
                    const int nq = (nbb + j * 8 + ((cc == 2) ? 4 : 0)) >> 2;
                    const int z = nq / LLn, t = nq - z * LLn;
                    const int m = mb + g8 + h * 8;
                    const bool keep = (MODE == 3) ? (z <= m) : (z <= t);
                    float4 r4;
                    if (keep) r4 = lsm4(a0, a1, p0, p1);
                    else      r4 = make_float4(LOGQ, LOGQ, LOGQ, LOGQ);
                    size_t qb;
                    if constexpr (MODE == 3)
                        qb = (((size_t)(zb * LLn + z) * LLn + m) * LLn + t);
                    else
                        qb = (((size_t)(zb * LLn + z) * LLn + t) * LLn + m);
                    ((float4*)outp)[qb] = r4;
                }
            }
        }
    }
}

// ---------------------------------------------------------------------------
extern "C" void kernel_launch(void* const* d_in, const int* in_sizes, int n_in,
                              void* d_out, int out_size)
{
    const float* x     = (const float*)d_in[0];
    const float* W_sh  = (const float*)d_in[1];
    const float* b_sh  = (const float*)d_in[2];
    const float* W_st  = (const float*)d_in[3];
    const float* b_st  = (const float*)d_in[4];
    const float* W_oh  = (const float*)d_in[5];
    const float* b_oh  = (const float*)d_in[6];
    const float* W_ot  = (const float*)d_in[7];
    const float* b_ot  = (const float*)d_in[8];
    const float* W_t1  = (const float*)d_in[9];
    const float* W_t2  = (const float*)d_in[10];
    float* out = (float*)d_out;

    cudaFuncSetAttribute(tk<0>, cudaFuncAttributeMaxDynamicSharedMemorySize, SMTOT);
    cudaFuncSetAttribute(tk<1>, cudaFuncAttributeMaxDynamicSharedMemorySize, SMTOT);
    cudaFuncSetAttribute(tk<2>, cudaFuncAttributeMaxDynamicSharedMemorySize, SMTOT);
    cudaFuncSetAttribute(tk<3>, cudaFuncAttributeMaxDynamicSharedMemorySize, SMTOT);
    cudaFuncSetAttribute(tk<4>, cudaFuncAttributeMaxDynamicSharedMemorySize, SMTOT);

    // prep: split inputs/weights into bf16 hi/lo
    prep_x<<<(BL * DIN + 255) / 256, 256>>>(x);
    prep_pw4<<<dim3((DT * DIN + 255) / 256, 4), 256>>>(W_sh, W_st, W_oh, W_ot);
    prep_wt2<<<dim3(OI, 25, 2), dim3(32, 32)>>>(W_t1, W_t2);

    // projections: M=288 (6x48) x N=150 (2 tiles of 128) x 4 sel
    tk<0><<<dim3(6, 2, 4), 192, SMTOT>>>(b_sh, b_st, b_oh, b_ot, nullptr, 0, 0);

    // triaffine 1: (x=st[1], y=oh[2], z=sh[0], W1)
    tk<1><<<dim3(6, 704, 1), 192, SMTOT>>>(nullptr, nullptr, nullptr, nullptr, nullptr, 0, 0);
    tk<2><<<dim3(3, 675, 2), 192, SMTOT>>>(nullptr, nullptr, nullptr, nullptr, nullptr, 2, 0);
    tk<3><<<dim3(3, 648, 2), 192, SMTOT>>>(nullptr, nullptr, nullptr, nullptr, out, 1, 0);

    // triaffine 2: (x=ot[3], y=st[1], z=sh[0], W2), transposed final coords
    tk<1><<<dim3(6, 704, 1), 192, SMTOT>>>(nullptr, nullptr, nullptr, nullptr, nullptr, 0, 1);
    tk<2><<<dim3(3, 675, 2), 192, SMTOT>>>(nullptr, nullptr, nullptr, nullptr, nullptr, 1, 0);
    tk<4><<<dim3(3, 648, 2), 192, SMTOT>>>(nullptr, nullptr, nullptr, nullptr, out + OUT1N, 3, 0);
}

// round 13
// speedup vs baseline: 1.1014x; 1.0581x over previous
#include <cuda_runtime.h>
#include <cuda_bf16.h>
#include <math.h>
#include <stdint.h>

// ---------------- problem constants ----------------
#define LLn   144
#define DIN   1024
#define DT    150
#define DTP   160
#define NOUT  4
#define BL    288
#define BZO   1152
#define OI    600
#define NFLAT 90000          // OI*DT      (flattened op1 N)
#define NF2   86400          // 576*DT     (flattened op2 N per batch)
#define NF3   82944          // 576*LLn    (flattened op3 N per batch)
#define OUT1N 23887872
#define LOGQ  -1.3862943611198906f

// ---------------- scratch (device globals, bf16 hi/lo splits) -------------
// pad columns [150,160) of g_w / g_t are never written -> stay zero (load-time
// zero-init), which is exactly what the K=160 consumers need.
__device__ __align__(256) __nv_bfloat16 g_xh[BL*DIN],        g_xl[BL*DIN];
__device__ __align__(256) __nv_bfloat16 g_Wph[4][DT*DIN],    g_Wpl[4][DT*DIN];   // [sel][n][k]
__device__ __align__(256) __nv_bfloat16 g_Wth[2][OI*DT*DTP], g_Wtl[2][OI*DT*DTP];// [tri][(oi,j)][k]
__device__ __align__(256) __nv_bfloat16 g_ph[4][BL*DTP],     g_pl[4][BL*DTP];
__device__ __align__(256) __nv_bfloat16 g_wh[2][(size_t)BZO*DT*DTP],  g_wl[2][(size_t)BZO*DT*DTP];
// g_t rows per batch: (z*144+y)*4+o  (o innermost -> softmax quads adjacent)
__device__ __align__(256) __nv_bfloat16 g_th[2][(size_t)BZO*LLn*DTP], g_tl[2][(size_t)BZO*LLn*DTP];

// ---------------- helpers ----------------
__device__ __forceinline__ void split2(float v, __nv_bfloat16& h, __nv_bfloat16& l) {
    h = __float2bfloat16_rn(v);
    l = __float2bfloat16_rn(v - __bfloat162float(h));
}
__device__ __forceinline__ void store_pair(__nv_bfloat16* baseH, __nv_bfloat16* baseL,
                                           size_t d, float v0, float v1) {
    __nv_bfloat16 h0, l0, h1, l1;
    split2(v0, h0, l0);
    split2(v1, h1, l1);
    uint32_t ph = (uint32_t)__bfloat16_as_ushort(h0) | ((uint32_t)__bfloat16_as_ushort(h1) << 16);
    uint32_t pl = (uint32_t)__bfloat16_as_ushort(l0) | ((uint32_t)__bfloat16_as_ushort(l1) << 16);
    *(uint32_t*)(baseH + d) = ph;
    *(uint32_t*)(baseL + d) = pl;
}
__device__ __forceinline__ uint32_t smem_u32(const void* p) {
    uint32_t a;
    asm("{ .reg .u64 t; cvta.to.shared.u64 t, %1; cvt.u32.u64 %0, t; }" : "=r"(a) : "l"(p));
    return a;
}
__device__ __forceinline__ void ldm4(uint32_t* d, uint32_t addr) {
    asm volatile("ldmatrix.sync.aligned.m8n8.x4.shared.b16 {%0,%1,%2,%3}, [%4];"
        : "=r"(d[0]), "=r"(d[1]), "=r"(d[2]), "=r"(d[3]) : "r"(addr));
}
__device__ __forceinline__ void mma_bf16(float* c, const uint32_t* a, uint32_t b0, uint32_t b1) {
    asm volatile("mma.sync.aligned.m16n8k16.row.col.f32.bf16.bf16.f32 "
        "{%0,%1,%2,%3}, {%4,%5,%6,%7}, {%8,%9}, {%0,%1,%2,%3};"
        : "+f"(c[0]), "+f"(c[1]), "+f"(c[2]), "+f"(c[3])
        : "r"(a[0]), "r"(a[1]), "r"(a[2]), "r"(a[3]), "r"(b0), "r"(b1));
}
__device__ __forceinline__ void cpa16(uint32_t dst, const void* src, uint32_t sz) {
    asm volatile("cp.async.cg.shared.global [%0], [%1], 16, %2;"
        :: "r"(dst), "l"(src), "r"(sz) : "memory");
}
template<int N> __device__ __forceinline__ void cp_wait() {
    asm volatile("cp.async.wait_group %0;" :: "n"(N) : "memory");
}
__device__ __forceinline__ float4 lsm4(float a, float b, float c, float d) {
    float m = fmaxf(fmaxf(a, b), fmaxf(c, d));
    float s = expf(a - m) + expf(b - m) + expf(c - m) + expf(d - m);
    float l = m + logf(s);
    return make_float4(a - l, b - l, c - l, d - l);
}

// ---------------- prep kernels ----------------
__global__ void prep_x(const float* __restrict__ x) {
    int i = blockIdx.x * 256 + threadIdx.x;
    if (i >= BL * DIN) return;
    split2(x[i], g_xh[i], g_xl[i]);
}
__global__ void prep_pw4(const float* __restrict__ W0, const float* __restrict__ W1,
                         const float* __restrict__ W2, const float* __restrict__ W3) {
    int i = blockIdx.x * 256 + threadIdx.x;
    if (i >= DT * DIN) return;
    int sel = blockIdx.y;
    const float* W = (sel == 0) ? W0 : (sel == 1) ? W1 : (sel == 2) ? W2 : W3;
    int n = i >> 10, k = i & 1023;
    split2(__ldg(&W[k * DT + n]), g_Wph[sel][i], g_Wpl[sel][i]);
}
__global__ void prep_wt2(const float* __restrict__ Wa, const float* __restrict__ Wb) {
    __shared__ float t[32][33];
    int oi = blockIdx.x;
    int tri = blockIdx.z;
    const float* W = tri ? Wb : Wa;
    int kt = (blockIdx.y / 5) * 32, jt = (blockIdx.y % 5) * 32;
    int tx = threadIdx.x, ty = threadIdx.y;
    int k = kt + ty, j = jt + tx;
    float v = (k < DT && j < DT) ? W[(size_t)oi * (DT * DT) + k * DT + j] : 0.f;
    t[ty][tx] = v;
    __syncthreads();
    int j2 = jt + ty, k2 = kt + tx;
    if (j2 < DT && k2 < DTP) {
        float u = t[tx][ty];
        size_t d = (size_t)oi * (DT * DTP) + (size_t)j2 * DTP + k2;
        split2(u, g_Wth[tri][d], g_Wtl[tri][d]);
    }
}

// ---------------- HMMA GEMM: BM=48, BN=96, BK=32, 192 thr, STAGES-buffered -
// smem/stage: Ah[48x80B] Al Bh[96x80B] Bl = 23040B; STAGES stages (dynamic).
// Warp grid 3(m) x 2(n): each warp 16m x 48n = 6 acc quads.
// MODE 0: proj   x(288x1024) @ Wp[z](as [n][k]) -> g_p[z]   (z=sel, 4 stages)
// MODE 1: op1    sh(288xDTP) @ Wt[z] flat N=90000 -> g_w[z] (z=tri)
// MODE 2: op2    Y_b @ g_w[tr][b] flat N=86400 -> g_t[tr]   (z=b*2+tr)
// MODE 3: op3/1  X_b @ g_t[0][b] flat N=82944 -> out, fused logsoftmax (z=b)
// MODE 4: op3/2  same on g_t[1], transposed final coords (z=b)
#define STG    23040
#define OFF_AL 3840
#define OFF_BH 7680
#define OFF_BL 15360
#define NIT    6            // 1152 segments / 192 threads (exact)

template<int MODE, int STAGES>
__global__ __launch_bounds__(192)
void tk(const float* __restrict__ b0s, const float* __restrict__ b1s,
        const float* __restrict__ b2s, const float* __restrict__ b3s,
        float* __restrict__ outp)
{
    extern __shared__ __align__(16) char sm[];

    const int tid  = threadIdx.x;
    const int lane = tid & 31, warp = tid >> 5;
    const int wm = warp >> 1, wn = warp & 1;
    const int bx = blockIdx.x, by = blockIdx.y, zb = blockIdx.z;
    const int m0 = bx * 48, n0 = by * 96;

    // ---- fully-masked block: fill constants, skip GEMM ----
    if constexpr (MODE == 3 || MODE == 4) {
        bool allmask;
        if constexpr (MODE == 3) {
            allmask = ((n0 >> 2) / LLn) > (m0 + 47);
        } else {
            allmask = true;
            #pragma unroll 1
            for (int qd = 0; qd < 24; qd++) {
                int nq = (n0 >> 2) + qd;
                if (nq / LLn <= nq % LLn) { allmask = false; break; }
            }
        }
        if (allmask) {
            const float4 c4 = make_float4(LOGQ, LOGQ, LOGQ, LOGQ);
            for (int idx = tid; idx < 48 * 24; idx += 192) {
                int mm = m0 + idx / 24;
                int nq = (n0 >> 2) + idx % 24;
                int z = nq / LLn, t = nq % LLn;
                size_t qb;
                if constexpr (MODE == 3)
                    qb = (((size_t)(zb * LLn + z) * LLn + mm) * LLn + t);
                else
                    qb = (((size_t)(zb * LLn + z) * LLn + t) * LLn + mm);
                ((float4*)outp)[qb] = c4;
            }
            return;
        }
    }

    const __nv_bfloat16 *Ah, *Al, *Bh, *Bl;
    int pitchA, pitchB, KT, NB;
    if constexpr (MODE == 0) {
        Ah = g_xh; Al = g_xl; Bh = g_Wph[zb]; Bl = g_Wpl[zb];
        pitchA = DIN; pitchB = DIN; KT = 32; NB = DT;
    }
    if constexpr (MODE == 1) {
        Ah = g_ph[0]; Al = g_pl[0]; Bh = g_Wth[zb]; Bl = g_Wtl[zb];
        pitchA = DTP; pitchB = DTP; KT = 5; NB = NFLAT;
    }
    if constexpr (MODE == 2) {
        const int tr = zb & 1, b = zb >> 1;
        const int sl = tr ? 1 : 2;                 // tri1: Y=oh, tri2: Y=st
        Ah = g_ph[sl] + (size_t)b * LLn * DTP; Al = g_pl[sl] + (size_t)b * LLn * DTP;
        Bh = g_wh[tr] + (size_t)b * 576 * DT * DTP;
        Bl = g_wl[tr] + (size_t)b * 576 * DT * DTP;
        pitchA = DTP; pitchB = DTP; KT = 5; NB = NF2;
    }
    if constexpr (MODE == 3) {
        Ah = g_ph[1] + (size_t)zb * LLn * DTP; Al = g_pl[1] + (size_t)zb * LLn * DTP;
        Bh = g_th[0] + (size_t)zb * NF3 * DTP; Bl = g_tl[0] + (size_t)zb * NF3 * DTP;
        pitchA = DTP; pitchB = DTP; KT = 5; NB = NF3;
    }
    if constexpr (MODE == 4) {
        Ah = g_ph[3] + (size_t)zb * LLn * DTP; Al = g_pl[3] + (size_t)zb * LLn * DTP;
        Bh = g_th[1] + (size_t)zb * NF3 * DTP; Bl = g_tl[1] + (size_t)zb * NF3 * DTP;
        pitchA = DTP; pitchB = DTP; KT = 5; NB = NF3;
    }

    const uint32_t sbase = smem_u32(sm);

    // ---- precompute per-thread staging plan: NIT segments of 16B (exact) ----
    const __nv_bfloat16* sptr[NIT];
    uint32_t sdst[NIT], ssz[NIT];
    #pragma unroll
    for (int it = 0; it < NIT; it++) {
        int idx = tid + it * 192;                    // 0..1151
        if (idx < 384) {
            int mat = idx / 192;                     // 0=Ah 1=Al
            int rem = idx - mat * 192;
            int row = rem >> 2, seg = rem & 3;
            sptr[it] = (mat ? Al : Ah) + (size_t)(m0 + row) * pitchA + seg * 8;
            sdst[it] = (uint32_t)(mat * OFF_AL + row * 80 + seg * 16);
            ssz[it]  = 16;
        } else {
            int rem = idx - 384;                     // 0..767
            int mat = (rem < 384) ? 0 : 1;           // 0=Bh 1=Bl
            int brem = (rem < 384) ? rem : rem - 384;
            int row = brem >> 2, seg = brem & 3;
            int gr = n0 + row;
            bool vv = gr < NB;
            sptr[it] = ((mat == 1) ? Bl : Bh) + (size_t)(vv ? gr : n0) * pitchB + seg * 8;
            sdst[it] = (uint32_t)(OFF_BH + mat * 7680 + row * 80 + seg * 16);
            ssz[it]  = vv ? 16u : 0u;
        }
    }

    // ---- ldmatrix lane offsets (pitch-80 rows, conflict-free) ----
    const int q = lane >> 3, r = lane & 7;
    const uint32_t aOff  = (uint32_t)((wm * 16 + ((q & 1) ? 8 : 0) + r) * 80 + ((q >> 1) ? 16 : 0));
    const uint32_t bOff0 = (uint32_t)((wn * 48 + ((lane >> 4) ? 8 : 0) + r) * 80 + ((q & 1) ? 16 : 0));

    // MODE3: warp-level compute skip when this warp's m-range is fully masked
    bool wskip = false;
    if constexpr (MODE == 3)
        wskip = ((n0 >> 2) / LLn) > (m0 + wm * 16 + 15);

    float acc[6][4];
    #pragma unroll
    for (int i = 0; i < 6; i++)
        #pragma unroll
        for (int j = 0; j < 4; j++) acc[i][j] = 0.f;

    auto stageCh = [&](int buf) {
        const uint32_t sb = sbase + (uint32_t)(buf * STG);
        #pragma unroll
        for (int it = 0; it < NIT; it++) {
            cpa16(sb + sdst[it], sptr[it], ssz[it]);
            sptr[it] += 32;
        }
        asm volatile("cp.async.commit_group;" ::: "memory");
    };

    // prologue: stage first STAGES-1 chunks
    #pragma unroll
    for (int s = 0; s < STAGES - 1; s++) stageCh(s);

    for (int ch = 0; ch < KT; ch++) {
        if (ch + STAGES - 1 < KT) {
            stageCh((ch + STAGES - 1) & (STAGES - 1));
            cp_wait<STAGES - 1>();
        } else {
            if constexpr (STAGES == 2) {
                cp_wait<0>();
            } else {
                int v = KT - 1 - ch;
                if (v >= 2) cp_wait<2>();
                else if (v == 1) cp_wait<1>();
                else cp_wait<0>();
            }
        }
        __syncthreads();

        if (!wskip) {
            const uint32_t cb = sbase + (uint32_t)((ch & (STAGES - 1)) * STG);
            #pragma unroll
            for (int ks = 0; ks < 2; ks++) {
                const uint32_t ko = (uint32_t)(ks * 32);
                uint32_t ah[4], al4[4];
                ldm4(ah,  cb + aOff + ko);
                ldm4(al4, cb + OFF_AL + aOff + ko);
                #pragma unroll
                for (int g = 0; g < 3; g++) {
                    uint32_t bh[4], bl[4];
                    const uint32_t bo = bOff0 + (uint32_t)(g * 1280) + ko;
                    ldm4(bh, cb + OFF_BH + bo);
                    ldm4(bl, cb + OFF_BL + bo);
                    mma_bf16(acc[2 * g],     ah,  bh[0], bh[1]);
                    mma_bf16(acc[2 * g],     ah,  bl[0], bl[1]);
                    mma_bf16(acc[2 * g],     al4, bh[0], bh[1]);
                    mma_bf16(acc[2 * g + 1], ah,  bh[2], bh[3]);
                    mma_bf16(acc[2 * g + 1], ah,  bl[2], bl[3]);
                    mma_bf16(acc[2 * g + 1], al4, bh[2], bh[3]);
                }
            }
        }
        __syncthreads();
    }

    // ---- store ----
    const float* bias = nullptr;
    if constexpr (MODE == 0)
        bias = (zb == 0) ? b0s : (zb == 1) ? b1s : (zb == 2) ? b2s : b3s;

    const int g8 = lane >> 2, cc = lane & 3, t2 = cc * 2;
    const int mb = m0 + wm * 16, nbb = n0 + wn * 48;

    if constexpr (MODE <= 2) {
        // pair-packed bf16 stores (even n; rows even-width so pairs never straddle)
        #pragma unroll
        for (int j = 0; j < 6; j++) {
            #pragma unroll
            for (int h = 0; h < 2; h++) {
                const int m = mb + g8 + h * 8;
                const int n = nbb + j * 8 + t2;          // even
                const float v0 = acc[j][2 * h], v1 = acc[j][2 * h + 1];
                if constexpr (MODE == 0) {
                    if (n + 1 < DTP) {
                        float a0 = (n < DT) ? v0 + bias[n] : 0.f;
                        float a1 = (n + 1 < DT) ? v1 + bias[n + 1] : 0.f;
                        store_pair(g_ph[zb], g_pl[zb], (size_t)m * DTP + n, a0, a1);
                    }
                }
                if constexpr (MODE == 1) {
                    if (n < NFLAT) {
                        int oi = n / DT, jj = n - oi * DT;
                        int o = oi / DT, i = oi - o * DT;
                        size_t d = ((size_t)(m * NOUT + o) * DT + i) * DTP + jj;
                        store_pair(g_wh[zb], g_wl[zb], d, v0, v1);
                    }
                }
                if constexpr (MODE == 2) {
                    const int tr = zb & 1, b = zb >> 1;
                    int qq = n / DT, i = n - qq * DT;
                    int z = qq >> 2, o = qq & 3;
                    size_t rrow = ((size_t)(z * LLn + m)) * NOUT + o;
                    size_t d = ((size_t)b * NF3 + rrow) * DTP + i;
                    store_pair(g_th[tr], g_tl[tr], d, v0, v1);
                }
            }
        }
    } else {
        // fused mask + log_softmax; one float4 per quad, even-cc lanes store
        #pragma unroll
        for (int j = 0; j < 6; j++) {
            #pragma unroll
            for (int h = 0; h < 2; h++) {
                const float a0 = acc[j][2 * h], a1 = acc[j][2 * h + 1];
                const float p0 = __shfl_xor_sync(0xffffffffu, a0, 1);
                const float p1 = __shfl_xor_sync(0xffffffffu, a1, 1);
                if (!(cc & 1)) {
                    const int nq = (nbb + j * 8 + ((cc == 2) ? 4 : 0)) >> 2;
                    const int z = nq / LLn, t = nq - z * LLn;
                    const int m = mb + g8 + h * 8;
                    const bool keep = (MODE == 3) ? (z <= m) : (z <= t);
                    float4 r4;
                    if (keep) r4 = lsm4(a0, a1, p0, p1);
                    else      r4 = make_float4(LOGQ, LOGQ, LOGQ, LOGQ);
                    size_t qb;
                    if constexpr (MODE == 3)
                        qb = (((size_t)(zb * LLn + z) * LLn + m) * LLn + t);
                    else
                        qb = (((size_t)(zb * LLn + z) * LLn + t) * LLn + m);
                    ((float4*)outp)[qb] = r4;
                }
            }
        }
    }
}

// ---------------------------------------------------------------------------
extern "C" void kernel_launch(void* const* d_in, const int* in_sizes, int n_in,
                              void* d_out, int out_size)
{
    const float* x     = (const float*)d_in[0];
    const float* W_sh  = (const float*)d_in[1];
    const float* b_sh  = (const float*)d_in[2];
    const float* W_st  = (const float*)d_in[3];
    const float* b_st  = (const float*)d_in[4];
    const float* W_oh  = (const float*)d_in[5];
    const float* b_oh  = (const float*)d_in[6];
    const float* W_ot  = (const float*)d_in[7];
    const float* b_ot  = (const float*)d_in[8];
    const float* W_t1  = (const float*)d_in[9];
    const float* W_t2  = (const float*)d_in[10];
    float* out = (float*)d_out;

    cudaFuncSetAttribute(tk<0, 4>, cudaFuncAttributeMaxDynamicSharedMemorySize, 4 * STG);
    cudaFuncSetAttribute(tk<1, 2>, cudaFuncAttributeMaxDynamicSharedMemorySize, 2 * STG);
    cudaFuncSetAttribute(tk<2, 2>, cudaFuncAttributeMaxDynamicSharedMemorySize, 2 * STG);
    cudaFuncSetAttribute(tk<3, 2>, cudaFuncAttributeMaxDynamicSharedMemorySize, 2 * STG);
    cudaFuncSetAttribute(tk<4, 2>, cudaFuncAttributeMaxDynamicSharedMemorySize, 2 * STG);

    // prep: split inputs/weights into bf16 hi/lo
    prep_x<<<(BL * DIN + 255) / 256, 256>>>(x);
    prep_pw4<<<dim3((DT * DIN + 255) / 256, 4), 256>>>(W_sh, W_st, W_oh, W_ot);
    prep_wt2<<<dim3(OI, 25, 2), dim3(32, 32)>>>(W_t1, W_t2);

    // projections: M=288 (6x48) x N=150 (2x96) x 4 sel, 4-stage pipeline
    tk<0, 4><<<dim3(6, 2, 4), 192, 4 * STG>>>(b_sh, b_st, b_oh, b_ot, nullptr);

    // op1 both tris:  z = tri
    tk<1, 2><<<dim3(6, 938, 2), 192, 2 * STG>>>(nullptr, nullptr, nullptr, nullptr, nullptr);
    // op2 both tris x both batches: z = b*2 + tri
    tk<2, 2><<<dim3(3, 900, 4), 192, 2 * STG>>>(nullptr, nullptr, nullptr, nullptr, nullptr);
    // op3 tri1 (direct) and tri2 (transposed), z = batch
    tk<3, 2><<<dim3(3, 864, 2), 192, 2 * STG>>>(nullptr, nullptr, nullptr, nullptr, out);
    tk<4, 2><<<dim3(3, 864, 2), 192, 2 * STG>>>(nullptr, nullptr, nullptr, nullptr, out + OUT1N);
}

// round 14
// speedup vs baseline: 1.6196x; 1.4704x over previous
#include <cuda_runtime.h>
#include <cuda_fp16.h>
#include <math.h>
#include <stdint.h>

// ---------------- problem constants ----------------
#define LLn   144
#define DIN   1024
#define DT    150
#define DTP   160
#define NOUT  4
#define BL    288
#define BZO   1152
#define OI    600
#define NFLAT 90000          // OI*DT      (flattened op1 N)
#define NF2   86400          // 576*DT     (flattened op2 N per batch)
#define NF3   82944          // 576*LLn    (flattened op3 N per batch)
#define OUT1N 23887872
#define LOGQ  -1.3862943611198906f

// ---------------- scratch (device globals, fp16) -------------
// A-side operands keep hi/lo split (exact to ~2^-22); B-side single fp16.
// pad cols [150,160) never written -> stay zero, as K=160 consumers need.
__device__ __align__(256) __half g_xh[BL*DIN],  g_xl[BL*DIN];
__device__ __align__(256) __half g_Wp[4][DT*DIN];                  // [sel][n][k] single
__device__ __align__(256) __half g_Wt[2][OI*DT*DTP];               // [tri][(oi,j)][k] single
__device__ __align__(256) __half g_ph[4][BL*DTP], g_pl[4][BL*DTP]; // projections h/l
__device__ __align__(256) __half g_w[2][(size_t)BZO*DT*DTP];       // single
// g_t rows per batch: (z*144+y)*4+o  (o innermost -> softmax quads adjacent)
__device__ __align__(256) __half g_t[2][(size_t)BZO*LLn*DTP];      // single

// ---------------- helpers ----------------
__device__ __forceinline__ void split2(float v, __half& h, __half& l) {
    h = __float2half_rn(v);
    l = __float2half_rn(v - __half2float(h));
}
// hi/lo pair store (projections)
__device__ __forceinline__ void store_pair2(__half* baseH, __half* baseL,
                                            size_t d, float v0, float v1) {
    __half h0, l0, h1, l1;
    split2(v0, h0, l0);
    split2(v1, h1, l1);
    uint32_t ph = (uint32_t)__half_as_ushort(h0) | ((uint32_t)__half_as_ushort(h1) << 16);
    uint32_t pl = (uint32_t)__half_as_ushort(l0) | ((uint32_t)__half_as_ushort(l1) << 16);
    *(uint32_t*)(baseH + d) = ph;
    *(uint32_t*)(baseL + d) = pl;
}
// single fp16 pair store (intermediates w, t)
__device__ __forceinline__ void store_pair1(__half* base, size_t d, float v0, float v1) {
    uint32_t p = (uint32_t)__half_as_ushort(__float2half_rn(v0))
               | ((uint32_t)__half_as_ushort(__float2half_rn(v1)) << 16);
    *(uint32_t*)(base + d) = p;
}
__device__ __forceinline__ uint32_t smem_u32(const void* p) {
    uint32_t a;
    asm("{ .reg .u64 t; cvta.to.shared.u64 t, %1; cvt.u32.u64 %0, t; }" : "=r"(a) : "l"(p));
    return a;
}
__device__ __forceinline__ void ldm4(uint32_t* d, uint32_t addr) {
    asm volatile("ldmatrix.sync.aligned.m8n8.x4.shared.b16 {%0,%1,%2,%3}, [%4];"
        : "=r"(d[0]), "=r"(d[1]), "=r"(d[2]), "=r"(d[3]) : "r"(addr));
}
__device__ __forceinline__ void mma_f16(float* c, const uint32_t* a, uint32_t b0, uint32_t b1) {
    asm volatile("mma.sync.aligned.m16n8k16.row.col.f32.f16.f16.f32 "
        "{%0,%1,%2,%3}, {%4,%5,%6,%7}, {%8,%9}, {%0,%1,%2,%3};"
        : "+f"(c[0]), "+f"(c[1]), "+f"(c[2]), "+f"(c[3])
        : "r"(a[0]), "r"(a[1]), "r"(a[2]), "r"(a[3]), "r"(b0), "r"(b1));
}
__device__ __forceinline__ void cpa16(uint32_t dst, const void* src, uint32_t sz) {
    asm volatile("cp.async.cg.shared.global [%0], [%1], 16, %2;"
        :: "r"(dst), "l"(src), "r"(sz) : "memory");
}
template<int N> __device__ __forceinline__ void cp_wait() {
    asm volatile("cp.async.wait_group %0;" :: "n"(N) : "memory");
}
__device__ __forceinline__ float4 lsm4(float a, float b, float c, float d) {
    float m = fmaxf(fmaxf(a, b), fmaxf(c, d));
    float s = expf(a - m) + expf(b - m) + expf(c - m) + expf(d - m);
    float l = m + logf(s);
    return make_float4(a - l, b - l, c - l, d - l);
}

// ---------------- prep kernels ----------------
__global__ void prep_x(const float* __restrict__ x) {
    int i = blockIdx.x * 256 + threadIdx.x;
    if (i >= BL * DIN) return;
    split2(x[i], g_xh[i], g_xl[i]);
}
__global__ void prep_pw4(const float* __restrict__ W0, const float* __restrict__ W1,
                         const float* __restrict__ W2, const float* __restrict__ W3) {
    int i = blockIdx.x * 256 + threadIdx.x;
    if (i >= DT * DIN) return;
    int sel = blockIdx.y;
    const float* W = (sel == 0) ? W0 : (sel == 1) ? W1 : (sel == 2) ? W2 : W3;
    int n = i >> 10, k = i & 1023;
    g_Wp[sel][i] = __float2half_rn(__ldg(&W[k * DT + n]));
}
__global__ void prep_wt2(const float* __restrict__ Wa, const float* __restrict__ Wb) {
    __shared__ float t[32][33];
    int oi = blockIdx.x;
    int tri = blockIdx.z;
    const float* W = tri ? Wb : Wa;
    int kt = (blockIdx.y / 5) * 32, jt = (blockIdx.y % 5) * 32;
    int tx = threadIdx.x, ty = threadIdx.y;
    int k = kt + ty, j = jt + tx;
    float v = (k < DT && j < DT) ? W[(size_t)oi * (DT * DT) + k * DT + j] : 0.f;
    t[ty][tx] = v;
    __syncthreads();
    int j2 = jt + ty, k2 = kt + tx;
    if (j2 < DT && k2 < DTP) {
        float u = t[tx][ty];
        size_t d = (size_t)oi * (DT * DTP) + (size_t)j2 * DTP + k2;
        g_Wt[tri][d] = __float2half_rn(u);
    }
}

// ---------------- HMMA GEMM: BM=48, BN=96, BK=32, 192 thr, 2-term fp16 -----
// A = hi/lo fp16 split (2 mats), B = single fp16 (1 mat).
// smem/stage: Ah[48x80B] Al Bh[96x80B] = 15360B; STAGES stages (dynamic).
// Warp grid 3(m) x 2(n): each warp 16m x 48n = 6 acc quads; 24 MMA/chunk/warp.
// MODE 0: proj   x(288x1024) @ Wp[z] -> g_p[z] h/l        (z=sel, 4 stages)
// MODE 1: op1    sh(288xDTP) @ Wt[z] flat N=90000 -> g_w[z] (z=tri)
// MODE 2: op2    Y_b @ g_w[tr][b] flat N=86400 -> g_t[tr]   (z=b*2+tr)
// MODE 3: op3/1  X_b @ g_t[0][b] flat N=82944 -> out, fused logsoftmax (z=b)
// MODE 4: op3/2  same on g_t[1], transposed final coords (z=b)
#define STG    15360
#define OFF_AL 3840
#define OFF_BH 7680
#define NIT    4            // 768 segments / 192 threads (exact)

template<int MODE, int STAGES>
__global__ __launch_bounds__(192)
void tk(const float* __restrict__ b0s, const float* __restrict__ b1s,
        const float* __restrict__ b2s, const float* __restrict__ b3s,
        float* __restrict__ outp)
{
    extern __shared__ __align__(16) char sm[];

    const int tid  = threadIdx.x;
    const int lane = tid & 31, warp = tid >> 5;
    const int wm = warp >> 1, wn = warp & 1;
    const int bx = blockIdx.x, by = blockIdx.y, zb = blockIdx.z;
    const int m0 = bx * 48, n0 = by * 96;

    // ---- fully-masked block: fill constants, skip GEMM ----
    if constexpr (MODE == 3 || MODE == 4) {
        bool allmask;
        if constexpr (MODE == 3) {
            allmask = ((n0 >> 2) / LLn) > (m0 + 47);
        } else {
            allmask = true;
            #pragma unroll 1
            for (int qd = 0; qd < 24; qd++) {
                int nq = (n0 >> 2) + qd;
                if (nq / LLn <= nq % LLn) { allmask = false; break; }
            }
        }
        if (allmask) {
            const float4 c4 = make_float4(LOGQ, LOGQ, LOGQ, LOGQ);
            for (int idx = tid; idx < 48 * 24; idx += 192) {
                int mm = m0 + idx / 24;
                int nq = (n0 >> 2) + idx % 24;
                int z = nq / LLn, t = nq % LLn;
                size_t qb;
                if constexpr (MODE == 3)
                    qb = (((size_t)(zb * LLn + z) * LLn + mm) * LLn + t);
                else
                    qb = (((size_t)(zb * LLn + z) * LLn + t) * LLn + mm);
                ((float4*)outp)[qb] = c4;
            }
            return;
        }
    }

    const __half *Ah, *Al, *Bh;
    int pitchA, pitchB, KT, NB;
    if constexpr (MODE == 0) {
        Ah = g_xh; Al = g_xl; Bh = g_Wp[zb];
        pitchA = DIN; pitchB = DIN; KT = 32; NB = DT;
    }
    if constexpr (MODE == 1) {
        Ah = g_ph[0]; Al = g_pl[0]; Bh = g_Wt[zb];
        pitchA = DTP; pitchB = DTP; KT = 5; NB = NFLAT;
    }
    if constexpr (MODE == 2) {
        const int tr = zb & 1, b = zb >> 1;
        const int sl = tr ? 1 : 2;                 // tri1: Y=oh, tri2: Y=st
        Ah = g_ph[sl] + (size_t)b * LLn * DTP; Al = g_pl[sl] + (size_t)b * LLn * DTP;
        Bh = g_w[tr] + (size_t)b * 576 * DT * DTP;
        pitchA = DTP; pitchB = DTP; KT = 5; NB = NF2;
    }
    if constexpr (MODE == 3) {
        Ah = g_ph[1] + (size_t)zb * LLn * DTP; Al = g_pl[1] + (size_t)zb * LLn * DTP;
        Bh = g_t[0] + (size_t)zb * NF3 * DTP;
        pitchA = DTP; pitchB = DTP; KT = 5; NB = NF3;
    }
    if constexpr (MODE == 4) {
        Ah = g_ph[3] + (size_t)zb * LLn * DTP; Al = g_pl[3] + (size_t)zb * LLn * DTP;
        Bh = g_t[1] + (size_t)zb * NF3 * DTP;
        pitchA = DTP; pitchB = DTP; KT = 5; NB = NF3;
    }

    const uint32_t sbase = smem_u32(sm);

    // ---- per-thread staging plan: NIT segments of 16B (exact, 768 total) ----
    const __half* sptr[NIT];
    uint32_t sdst[NIT], ssz[NIT];
    #pragma unroll
    for (int it = 0; it < NIT; it++) {
        int idx = tid + it * 192;                    // 0..767
        if (idx < 384) {
            int mat = idx / 192;                     // 0=Ah 1=Al
            int rem = idx - mat * 192;
            int row = rem >> 2, seg = rem & 3;
            sptr[it] = (mat ? Al : Ah) + (size_t)(m0 + row) * pitchA + seg * 8;
            sdst[it] = (uint32_t)(mat * OFF_AL + row * 80 + seg * 16);
            ssz[it]  = 16;
        } else {
            int brem = idx - 384;                    // 0..383  (B rows 96 x 4 segs)
            int row = brem >> 2, seg = brem & 3;
            int gr = n0 + row;
            bool vv = gr < NB;
            sptr[it] = Bh + (size_t)(vv ? gr : n0) * pitchB + seg * 8;
            sdst[it] = (uint32_t)(OFF_BH + row * 80 + seg * 16);
            ssz[it]  = vv ? 16u : 0u;
        }
    }

    // ---- ldmatrix lane offsets (pitch-80 rows, conflict-free) ----
    const int q = lane >> 3, r = lane & 7;
    const uint32_t aOff  = (uint32_t)((wm * 16 + ((q & 1) ? 8 : 0) + r) * 80 + ((q >> 1) ? 16 : 0));
    const uint32_t bOff0 = (uint32_t)((wn * 48 + ((lane >> 4) ? 8 : 0) + r) * 80 + ((q & 1) ? 16 : 0));

    // MODE3: warp-level compute skip when this warp's m-range is fully masked
    bool wskip = false;
    if constexpr (MODE == 3)
        wskip = ((n0 >> 2) / LLn) > (m0 + wm * 16 + 15);

    float acc[6][4];
    #pragma unroll
    for (int i = 0; i < 6; i++)
        #pragma unroll
        for (int j = 0; j < 4; j++) acc[i][j] = 0.f;

    auto stageCh = [&](int buf) {
        const uint32_t sb = sbase + (uint32_t)(buf * STG);
        #pragma unroll
        for (int it = 0; it < NIT; it++) {
            cpa16(sb + sdst[it], sptr[it], ssz[it]);
            sptr[it] += 32;
        }
        asm volatile("cp.async.commit_group;" ::: "memory");
    };

    // prologue: stage first STAGES-1 chunks
    #pragma unroll
    for (int s = 0; s < STAGES - 1; s++) stageCh(s);

    for (int ch = 0; ch < KT; ch++) {
        if (ch + STAGES - 1 < KT) {
            stageCh((ch + STAGES - 1) & (STAGES - 1));
            cp_wait<STAGES - 1>();
        } else {
            if constexpr (STAGES == 2) {
                cp_wait<0>();
            } else {
                int v = KT - 1 - ch;
                if (v >= 2) cp_wait<2>();
                else if (v == 1) cp_wait<1>();
                else cp_wait<0>();
            }
        }
        __syncthreads();

        if (!wskip) {
            const uint32_t cb = sbase + (uint32_t)((ch & (STAGES - 1)) * STG);
            #pragma unroll
            for (int ks = 0; ks < 2; ks++) {
                const uint32_t ko = (uint32_t)(ks * 32);
                uint32_t ah[4], al4[4];
                ldm4(ah,  cb + aOff + ko);
                ldm4(al4, cb + OFF_AL + aOff + ko);
                #pragma unroll
                for (int g = 0; g < 3; g++) {
                    uint32_t bh[4];
                    const uint32_t bo = bOff0 + (uint32_t)(g * 1280) + ko;
                    ldm4(bh, cb + OFF_BH + bo);
                    mma_f16(acc[2 * g],     ah,  bh[0], bh[1]);
                    mma_f16(acc[2 * g],     al4, bh[0], bh[1]);
                    mma_f16(acc[2 * g + 1], ah,  bh[2], bh[3]);
                    mma_f16(acc[2 * g + 1], al4, bh[2], bh[3]);
                }
            }
        }
        __syncthreads();
    }

    // ---- store ----
    const float* bias = nullptr;
    if constexpr (MODE == 0)
        bias = (zb == 0) ? b0s : (zb == 1) ? b1s : (zb == 2) ? b2s : b3s;

    const int g8 = lane >> 2, cc = lane & 3, t2 = cc * 2;
    const int mb = m0 + wm * 16, nbb = n0 + wn * 48;

    if constexpr (MODE <= 2) {
        // pair-packed stores (even n; rows even-width so pairs never straddle)
        #pragma unroll
        for (int j = 0; j < 6; j++) {
            #pragma unroll
            for (int h = 0; h < 2; h++) {
                const int m = mb + g8 + h * 8;
                const int n = nbb + j * 8 + t2;          // even
                const float v0 = acc[j][2 * h], v1 = acc[j][2 * h + 1];
                if constexpr (MODE == 0) {
                    if (n + 1 < DTP) {
                        float a0 = (n < DT) ? v0 + bias[n] : 0.f;
                        float a1 = (n + 1 < DT) ? v1 + bias[n + 1] : 0.f;
                        store_pair2(g_ph[zb], g_pl[zb], (size_t)m * DTP + n, a0, a1);
                    }
                }
                if constexpr (MODE == 1) {
                    if (n < NFLAT) {
                        int oi = n / DT, jj = n - oi * DT;
                        int o = oi / DT, i = oi - o * DT;
                        size_t d = ((size_t)(m * NOUT + o) * DT + i) * DTP + jj;
                        store_pair1(g_w[zb], d, v0, v1);
                    }
                }
                if constexpr (MODE == 2) {
                    const int tr = zb & 1, b = zb >> 1;
                    int qq = n / DT, i = n - qq * DT;
                    int z = qq >> 2, o = qq & 3;
                    size_t rrow = ((size_t)(z * LLn + m)) * NOUT + o;
                    size_t d = ((size_t)b * NF3 + rrow) * DTP + i;
                    store_pair1(g_t[tr], d, v0, v1);
                }
            }
        }
    } else {
        // fused mask + log_softmax; one float4 per quad, even-cc lanes store
        #pragma unroll
        for (int j = 0; j < 6; j++) {
            #pragma unroll
            for (int h = 0; h < 2; h++) {
                const float a0 = acc[j][2 * h], a1 = acc[j][2 * h + 1];
                const float p0 = __shfl_xor_sync(0xffffffffu, a0, 1);
                const float p1 = __shfl_xor_sync(0xffffffffu, a1, 1);
                if (!(cc & 1)) {
                    const int nq = (nbb + j * 8 + ((cc == 2) ? 4 : 0)) >> 2;
                    const int z = nq / LLn, t = nq - z * LLn;
                    const int m = mb + g8 + h * 8;
                    const bool keep = (MODE == 3) ? (z <= m) : (z <= t);
                    float4 r4;
                    if (keep) r4 = lsm4(a0, a1, p0, p1);
                    else      r4 = make_float4(LOGQ, LOGQ, LOGQ, LOGQ);
                    size_t qb;
                    if constexpr (MODE == 3)
                        qb = (((size_t)(zb * LLn + z) * LLn + m) * LLn + t);
                    else
                        qb = (((size_t)(zb * LLn + z) * LLn + t) * LLn + m);
                    ((float4*)outp)[qb] = r4;
                }
            }
        }
    }
}

// ---------------------------------------------------------------------------
extern "C" void kernel_launch(void* const* d_in, const int* in_sizes, int n_in,
                              void* d_out, int out_size)
{
    const float* x     = (const float*)d_in[0];
    const float* W_sh  = (const float*)d_in[1];
    const float* b_sh  = (const float*)d_in[2];
    const float* W_st  = (const float*)d_in[3];
    const float* b_st  = (const float*)d_in[4];
    const float* W_oh  = (const float*)d_in[5];
    const float* b_oh  = (const float*)d_in[6];
    const float* W_ot  = (const float*)d_in[7];
    const float* b_ot  = (const float*)d_in[8];
    const float* W_t1  = (const float*)d_in[9];
    const float* W_t2  = (const float*)d_in[10];
    float* out = (float*)d_out;

    cudaFuncSetAttribute(tk<0, 4>, cudaFuncAttributeMaxDynamicSharedMemorySize, 4 * STG);
    cudaFuncSetAttribute(tk<1, 2>, cudaFuncAttributeMaxDynamicSharedMemorySize, 2 * STG);
    cudaFuncSetAttribute(tk<2, 2>, cudaFuncAttributeMaxDynamicSharedMemorySize, 2 * STG);
    cudaFuncSetAttribute(tk<3, 2>, cudaFuncAttributeMaxDynamicSharedMemorySize, 2 * STG);
    cudaFuncSetAttribute(tk<4, 2>, cudaFuncAttributeMaxDynamicSharedMemorySize, 2 * STG);

    // prep: fp16 conversions (x h/l split; weights single)
    prep_x<<<(BL * DIN + 255) / 256, 256>>>(x);
    prep_pw4<<<dim3((DT * DIN + 255) / 256, 4), 256>>>(W_sh, W_st, W_oh, W_ot);
    prep_wt2<<<dim3(OI, 25, 2), dim3(32, 32)>>>(W_t1, W_t2);

    // projections: M=288 (6x48) x N=150 (2x96) x 4 sel, 4-stage pipeline
    tk<0, 4><<<dim3(6, 2, 4), 192, 4 * STG>>>(b_sh, b_st, b_oh, b_ot, nullptr);

    // op1 both tris:  z = tri
    tk<1, 2><<<dim3(6, 938, 2), 192, 2 * STG>>>(nullptr, nullptr, nullptr, nullptr, nullptr);
    // op2 both tris x both batches: z = b*2 + tri
    tk<2, 2><<<dim3(3, 900, 4), 192, 2 * STG>>>(nullptr, nullptr, nullptr, nullptr, nullptr);
    // op3 tri1 (direct) and tri2 (transposed), z = batch
    tk<3, 2><<<dim3(3, 864, 2), 192, 2 * STG>>>(nullptr, nullptr, nullptr, nullptr, out);
    tk<4, 2><<<dim3(3, 864, 2), 192, 2 * STG>>>(nullptr, nullptr, nullptr, nullptr, out + OUT1N);
}

// round 15
// speedup vs baseline: 1.8793x; 1.1604x over previous
#include <cuda_runtime.h>
#include <cuda_fp16.h>
#include <math.h>
#include <stdint.h>

// ---------------- problem constants ----------------
#define LLn   144
#define DIN   1024
#define DT    150
#define DTP   160
#define NOUT  4
#define BL    288
#define BZO   1152
#define OI    600
#define NFLAT 90000          // OI*DT      (flattened op1 N)
#define NF2   86400          // 576*DT     (flattened op2 N per batch)
#define NF3   82944          // 576*LLn    (flattened op3 N per batch)
#define OUT1N 23887872
#define LOGQ  -1.3862943611198906f

// ---------------- scratch (device globals, fp16) -------------
// x keeps hi/lo split (proj GEMM exact to ~2^-22); everything downstream single.
// pad cols [150,160) never written -> stay zero, as K=160 consumers need.
__device__ __align__(256) __half g_xh[BL*DIN],  g_xl[BL*DIN];
__device__ __align__(256) __half g_Wp[4][DT*DIN];                  // [sel][n][k]
__device__ __align__(256) __half g_Wt[2][OI*DT*DTP];               // [tri][(oi,j)][k]
__device__ __align__(256) __half g_p[4][BL*DTP];                   // projections (single)
__device__ __align__(256) __half g_w[2][(size_t)BZO*DT*DTP];
// g_t rows per batch: (z*144+y)*4+o  (o innermost -> softmax quads adjacent)
__device__ __align__(256) __half g_t[2][(size_t)BZO*LLn*DTP];

// ---------------- helpers ----------------
__device__ __forceinline__ void split2(float v, __half& h, __half& l) {
    h = __float2half_rn(v);
    l = __float2half_rn(v - __half2float(h));
}
// single fp16 pair store
__device__ __forceinline__ void store_pair1(__half* base, size_t d, float v0, float v1) {
    uint32_t p = (uint32_t)__half_as_ushort(__float2half_rn(v0))
               | ((uint32_t)__half_as_ushort(__float2half_rn(v1)) << 16);
    *(uint32_t*)(base + d) = p;
}
__device__ __forceinline__ uint32_t smem_u32(const void* p) {
    uint32_t a;
    asm("{ .reg .u64 t; cvta.to.shared.u64 t, %1; cvt.u32.u64 %0, t; }" : "=r"(a) : "l"(p));
    return a;
}
__device__ __forceinline__ void ldm4(uint32_t* d, uint32_t addr) {
    asm volatile("ldmatrix.sync.aligned.m8n8.x4.shared.b16 {%0,%1,%2,%3}, [%4];"
        : "=r"(d[0]), "=r"(d[1]), "=r"(d[2]), "=r"(d[3]) : "r"(addr));
}
__device__ __forceinline__ void mma_f16(float* c, const uint32_t* a, uint32_t b0, uint32_t b1) {
    asm volatile("mma.sync.aligned.m16n8k16.row.col.f32.f16.f16.f32 "
        "{%0,%1,%2,%3}, {%4,%5,%6,%7}, {%8,%9}, {%0,%1,%2,%3};"
        : "+f"(c[0]), "+f"(c[1]), "+f"(c[2]), "+f"(c[3])
        : "r"(a[0]), "r"(a[1]), "r"(a[2]), "r"(a[3]), "r"(b0), "r"(b1));
}
__device__ __forceinline__ void cpa16(uint32_t dst, const void* src, uint32_t sz) {
    asm volatile("cp.async.cg.shared.global [%0], [%1], 16, %2;"
        :: "r"(dst), "l"(src), "r"(sz) : "memory");
}
template<int N> __device__ __forceinline__ void cp_wait() {
    asm volatile("cp.async.wait_group %0;" :: "n"(N) : "memory");
}
__device__ __forceinline__ float4 lsm4(float a, float b, float c, float d) {
    float m = fmaxf(fmaxf(a, b), fmaxf(c, d));
    float s = expf(a - m) + expf(b - m) + expf(c - m) + expf(d - m);
    float l = m + logf(s);
    return make_float4(a - l, b - l, c - l, d - l);
}

// ---------------- prep kernels ----------------
__global__ void prep_x(const float* __restrict__ x) {
    int i = blockIdx.x * 256 + threadIdx.x;
    if (i >= BL * DIN) return;
    split2(x[i], g_xh[i], g_xl[i]);
}
__global__ void prep_pw4(const float* __restrict__ W0, const float* __restrict__ W1,
                         const float* __restrict__ W2, const float* __restrict__ W3) {
    int i = blockIdx.x * 256 + threadIdx.x;
    if (i >= DT * DIN) return;
    int sel = blockIdx.y;
    const float* W = (sel == 0) ? W0 : (sel == 1) ? W1 : (sel == 2) ? W2 : W3;
    int n = i >> 10, k = i & 1023;
    g_Wp[sel][i] = __float2half_rn(__ldg(&W[k * DT + n]));
}
__global__ void prep_wt2(const float* __restrict__ Wa, const float* __restrict__ Wb) {
    __shared__ float t[32][33];
    int oi = blockIdx.x;
    int tri = blockIdx.z;
    const float* W = tri ? Wb : Wa;
    int kt = (blockIdx.y / 5) * 32, jt = (blockIdx.y % 5) * 32;
    int tx = threadIdx.x, ty = threadIdx.y;
    int k = kt + ty, j = jt + tx;
    float v = (k < DT && j < DT) ? W[(size_t)oi * (DT * DT) + k * DT + j] : 0.f;
    t[ty][tx] = v;
    __syncthreads();
    int j2 = jt + ty, k2 = kt + tx;
    if (j2 < DT && k2 < DTP) {
        float u = t[tx][ty];
        size_t d = (size_t)oi * (DT * DTP) + (size_t)j2 * DTP + k2;
        g_Wt[tri][d] = __float2half_rn(u);
    }
}

// ---------------- HMMA GEMM: BM=48, BN=96, BK=32, 192 thr, fp16 ------------
// MODE 0 keeps A hi/lo split (3 smem mats, 16 MMA/chunk/warp);
// modes 1-4 single x single (2 mats, 12 MMA/chunk/warp).
// Warp grid 3(m) x 2(n): each warp 16m x 48n = 6 acc quads.
// MODE 0: proj   x(288x1024) @ Wp[z] -> g_p[z]            (z=sel, 4 stages)
// MODE 1: op1    p0(288xDTP) @ Wt[z] flat N=90000 -> g_w[z] (z=tri)
// MODE 2: op2    Y_b @ g_w[tr][b] flat N=86400 -> g_t[tr]   (z=b*2+tr)
// MODE 3: op3/1  X_b @ g_t[0][b] flat N=82944 -> out, fused logsoftmax (z=b)
// MODE 4: op3/2  same on g_t[1], transposed final coords (z=b)
template<int MODE, int STAGES>
__global__ __launch_bounds__(192)
void tk(const float* __restrict__ b0s, const float* __restrict__ b1s,
        const float* __restrict__ b2s, const float* __restrict__ b3s,
        float* __restrict__ outp)
{
    constexpr bool ASPLIT = (MODE == 0);
    constexpr int OFFAL = 3840;                         // Al region (split only)
    constexpr int OFFB  = ASPLIT ? 7680 : 3840;
    constexpr int STGc  = OFFB + 7680;                  // 15360 / 11520
    constexpr int NITc  = ASPLIT ? 4 : 3;               // 768 / 576 segments

    extern __shared__ __align__(16) char sm[];

    const int tid  = threadIdx.x;
    const int lane = tid & 31, warp = tid >> 5;
    const int wm = warp >> 1, wn = warp & 1;
    const int bx = blockIdx.x, by = blockIdx.y, zb = blockIdx.z;
    const int m0 = bx * 48, n0 = by * 96;

    // ---- fully-masked block: fill constants, skip GEMM ----
    if constexpr (MODE == 3 || MODE == 4) {
        bool allmask;
        if constexpr (MODE == 3) {
            allmask = ((n0 >> 2) / LLn) > (m0 + 47);
        } else {
            allmask = true;
            #pragma unroll 1
            for (int qd = 0; qd < 24; qd++) {
                int nq = (n0 >> 2) + qd;
                if (nq / LLn <= nq % LLn) { allmask = false; break; }
            }
        }
        if (allmask) {
            const float4 c4 = make_float4(LOGQ, LOGQ, LOGQ, LOGQ);
            for (int idx = tid; idx < 48 * 24; idx += 192) {
                int mm = m0 + idx / 24;
                int nq = (n0 >> 2) + idx % 24;
                int z = nq / LLn, t = nq % LLn;
                size_t qb;
                if constexpr (MODE == 3)
                    qb = (((size_t)(zb * LLn + z) * LLn + mm) * LLn + t);
                else
                    qb = (((size_t)(zb * LLn + z) * LLn + t) * LLn + mm);
                ((float4*)outp)[qb] = c4;
            }
            return;
        }
    }

    const __half *Ah, *Al = nullptr, *Bh;
    int pitchA, pitchB, KT, NB;
    if constexpr (MODE == 0) {
        Ah = g_xh; Al = g_xl; Bh = g_Wp[zb];
        pitchA = DIN; pitchB = DIN; KT = 32; NB = DT;
    }
    if constexpr (MODE == 1) {
        Ah = g_p[0]; Bh = g_Wt[zb];
        pitchA = DTP; pitchB = DTP; KT = 5; NB = NFLAT;
    }
    if constexpr (MODE == 2) {
        const int tr = zb & 1, b = zb >> 1;
        const int sl = tr ? 1 : 2;                 // tri1: Y=oh, tri2: Y=st
        Ah = g_p[sl] + (size_t)b * LLn * DTP;
        Bh = g_w[tr] + (size_t)b * 576 * DT * DTP;
        pitchA = DTP; pitchB = DTP; KT = 5; NB = NF2;
    }
    if constexpr (MODE == 3) {
        Ah = g_p[1] + (size_t)zb * LLn * DTP;
        Bh = g_t[0] + (size_t)zb * NF3 * DTP;
        pitchA = DTP; pitchB = DTP; KT = 5; NB = NF3;
    }
    if constexpr (MODE == 4) {
        Ah = g_p[3] + (size_t)zb * LLn * DTP;
        Bh = g_t[1] + (size_t)zb * NF3 * DTP;
        pitchA = DTP; pitchB = DTP; KT = 5; NB = NF3;
    }

    const uint32_t sbase = smem_u32(sm);

    // ---- per-thread staging plan: NITc segments of 16B (exact) ----
    const __half* sptr[NITc];
    uint32_t sdst[NITc], ssz[NITc];
    constexpr int NA = ASPLIT ? 384 : 192;
    #pragma unroll
    for (int it = 0; it < NITc; it++) {
        int idx = tid + it * 192;
        if (idx < NA) {
            int mat = idx / 192;                     // 0=Ah 1=Al (split only)
            int rem = idx - mat * 192;
            int row = rem >> 2, seg = rem & 3;
            sptr[it] = ((mat && ASPLIT) ? Al : Ah) + (size_t)(m0 + row) * pitchA + seg * 8;
            sdst[it] = (uint32_t)(mat * OFFAL + row * 80 + seg * 16);
            ssz[it]  = 16;
        } else {
            int brem = idx - NA;                     // 0..383 (B rows 96 x 4 segs)
            int row = brem >> 2, seg = brem & 3;
            int gr = n0 + row;
            bool vv = gr < NB;
            sptr[it] = Bh + (size_t)(vv ? gr : n0) * pitchB + seg * 8;
            sdst[it] = (uint32_t)(OFFB + row * 80 + seg * 16);
            ssz[it]  = vv ? 16u : 0u;
        }
    }

    // ---- ldmatrix lane offsets (pitch-80 rows, conflict-free) ----
    const int q = lane >> 3, r = lane & 7;
    const uint32_t aOff  = (uint32_t)((wm * 16 + ((q & 1) ? 8 : 0) + r) * 80 + ((q >> 1) ? 16 : 0));
    const uint32_t bOff0 = (uint32_t)((wn * 48 + ((lane >> 4) ? 8 : 0) + r) * 80 + ((q & 1) ? 16 : 0));

    // MODE3: warp-level compute skip when this warp's m-range is fully masked
    bool wskip = false;
    if constexpr (MODE == 3)
        wskip = ((n0 >> 2) / LLn) > (m0 + wm * 16 + 15);

    float acc[6][4];
    #pragma unroll
    for (int i = 0; i < 6; i++)
        #pragma unroll
        for (int j = 0; j < 4; j++) acc[i][j] = 0.f;

    auto stageCh = [&](int buf) {
        const uint32_t sb = sbase + (uint32_t)(buf * STGc);
        #pragma unroll
        for (int it = 0; it < NITc; it++) {
            cpa16(sb + sdst[it], sptr[it], ssz[it]);
            sptr[it] += 32;
        }
        asm volatile("cp.async.commit_group;" ::: "memory");
    };

    // prologue: stage first STAGES-1 chunks
    #pragma unroll
    for (int s = 0; s < STAGES - 1; s++) stageCh(s);

    for (int ch = 0; ch < KT; ch++) {
        if (ch + STAGES - 1 < KT) {
            stageCh((ch + STAGES - 1) & (STAGES - 1));
            cp_wait<STAGES - 1>();
        } else {
            if constexpr (STAGES == 2) {
                cp_wait<0>();
            } else {
                int v = KT - 1 - ch;
                if (v >= 2) cp_wait<2>();
                else if (v == 1) cp_wait<1>();
                else cp_wait<0>();
            }
        }
        __syncthreads();

        if (!wskip) {
            const uint32_t cb = sbase + (uint32_t)((ch & (STAGES - 1)) * STGc);
            #pragma unroll
            for (int ks = 0; ks < 2; ks++) {
                const uint32_t ko = (uint32_t)(ks * 32);
                uint32_t ah[4], al4[4];
                ldm4(ah, cb + aOff + ko);
                if constexpr (ASPLIT) ldm4(al4, cb + OFFAL + aOff + ko);
                #pragma unroll
                for (int g = 0; g < 3; g++) {
                    uint32_t bh[4];
                    const uint32_t bo = bOff0 + (uint32_t)(g * 1280) + ko;
                    ldm4(bh, cb + OFFB + bo);
                    mma_f16(acc[2 * g],     ah,  bh[0], bh[1]);
                    mma_f16(acc[2 * g + 1], ah,  bh[2], bh[3]);
                    if constexpr (ASPLIT) {
                        mma_f16(acc[2 * g],     al4, bh[0], bh[1]);
                        mma_f16(acc[2 * g + 1], al4, bh[2], bh[3]);
                    }
                }
            }
        }
        __syncthreads();
    }

    // ---- store ----
    const float* bias = nullptr;
    if constexpr (MODE == 0)
        bias = (zb == 0) ? b0s : (zb == 1) ? b1s : (zb == 2) ? b2s : b3s;

    const int g8 = lane >> 2, cc = lane & 3, t2 = cc * 2;
    const int mb = m0 + wm * 16, nbb = n0 + wn * 48;

    if constexpr (MODE <= 2) {
        // pair-packed stores (even n; rows even-width so pairs never straddle)
        #pragma unroll
        for (int j = 0; j < 6; j++) {
            #pragma unroll
            for (int h = 0; h < 2; h++) {
                const int m = mb + g8 + h * 8;
                const int n = nbb + j * 8 + t2;          // even
                const float v0 = acc[j][2 * h], v1 = acc[j][2 * h + 1];
                if constexpr (MODE == 0) {
                    if (n + 1 < DTP) {
                        float a0 = (n < DT) ? v0 + bias[n] : 0.f;
                        float a1 = (n + 1 < DT) ? v1 + bias[n + 1] : 0.f;
                        store_pair1(g_p[zb], (size_t)m * DTP + n, a0, a1);
                    }
                }
                if constexpr (MODE == 1) {
                    if (n < NFLAT) {
                        int oi = n / DT, jj = n - oi * DT;
                        int o = oi / DT, i = oi - o * DT;
                        size_t d = ((size_t)(m * NOUT + o) * DT + i) * DTP + jj;
                        store_pair1(g_w[zb], d, v0, v1);
                    }
                }
                if constexpr (MODE == 2) {
                    const int tr = zb & 1, b = zb >> 1;
                    int qq = n / DT, i = n - qq * DT;
                    int z = qq >> 2, o = qq & 3;
                    size_t rrow = ((size_t)(z * LLn + m)) * NOUT + o;
                    size_t d = ((size_t)b * NF3 + rrow) * DTP + i;
                    store_pair1(g_t[tr], d, v0, v1);
                }
            }
        }
    } else {
        // fused mask + log_softmax; one float4 per quad, even-cc lanes store
        #pragma unroll
        for (int j = 0; j < 6; j++) {
            #pragma unroll
            for (int h = 0; h < 2; h++) {
                const float a0 = acc[j][2 * h], a1 = acc[j][2 * h + 1];
                const float p0 = __shfl_xor_sync(0xffffffffu, a0, 1);
                const float p1 = __shfl_xor_sync(0xffffffffu, a1, 1);
                if (!(cc & 1)) {
                    const int nq = (nbb + j * 8 + ((cc == 2) ? 4 : 0)) >> 2;
                    const int z = nq / LLn, t = nq - z * LLn;
                    const int m = mb + g8 + h * 8;
                    const bool keep = (MODE == 3) ? (z <= m) : (z <= t);
                    float4 r4;
                    if (keep) r4 = lsm4(a0, a1, p0, p1);
                    else      r4 = make_float4(LOGQ, LOGQ, LOGQ, LOGQ);
                    size_t qb;
                    if constexpr (MODE == 3)
                        qb = (((size_t)(zb * LLn + z) * LLn + m) * LLn + t);
                    else
                        qb = (((size_t)(zb * LLn + z) * LLn + t) * LLn + m);
                    ((float4*)outp)[qb] = r4;
                }
            }
        }
    }
}

// ---------------------------------------------------------------------------
extern "C" void kernel_launch(void* const* d_in, const int* in_sizes, int n_in,
                              void* d_out, int out_size)
{
    const float* x     = (const float*)d_in[0];
    const float* W_sh  = (const float*)d_in[1];
    const float* b_sh  = (const float*)d_in[2];
    const float* W_st  = (const float*)d_in[3];
    const float* b_st  = (const float*)d_in[4];
    const float* W_oh  = (const float*)d_in[5];
    const float* b_oh  = (const float*)d_in[6];
    const float* W_ot  = (const float*)d_in[7];
    const float* b_ot  = (const float*)d_in[8];
    const float* W_t1  = (const float*)d_in[9];
    const float* W_t2  = (const float*)d_in[10];
    float* out = (float*)d_out;

    cudaFuncSetAttribute(tk<0, 4>, cudaFuncAttributeMaxDynamicSharedMemorySize, 4 * 15360);
    cudaFuncSetAttribute(tk<1, 2>, cudaFuncAttributeMaxDynamicSharedMemorySize, 2 * 11520);
    cudaFuncSetAttribute(tk<2, 2>, cudaFuncAttributeMaxDynamicSharedMemorySize, 2 * 11520);
    cudaFuncSetAttribute(tk<3, 2>, cudaFuncAttributeMaxDynamicSharedMemorySize, 2 * 11520);
    cudaFuncSetAttribute(tk<4, 2>, cudaFuncAttributeMaxDynamicSharedMemorySize, 2 * 11520);

    // prep: fp16 conversions (x h/l split; weights single)
    prep_x<<<(BL * DIN + 255) / 256, 256>>>(x);
    prep_pw4<<<dim3((DT * DIN + 255) / 256, 4), 256>>>(W_sh, W_st, W_oh, W_ot);
    prep_wt2<<<dim3(OI, 25, 2), dim3(32, 32)>>>(W_t1, W_t2);

    // projections: M=288 (6x48) x N=150 (2x96) x 4 sel, 4-stage pipeline
    tk<0, 4><<<dim3(6, 2, 4), 192, 4 * 15360>>>(b_sh, b_st, b_oh, b_ot, nullptr);

    // op1 both tris:  z = tri
    tk<1, 2><<<dim3(6, 938, 2), 192, 2 * 11520>>>(nullptr, nullptr, nullptr, nullptr, nullptr);
    // op2 both tris x both batches: z = b*2 + tri
    tk<2, 2><<<dim3(3, 900, 4), 192, 2 * 11520>>>(nullptr, nullptr, nullptr, nullptr, nullptr);
    // op3 tri1 (direct) and tri2 (transposed), z = batch
    tk<3, 2><<<dim3(3, 864, 2), 192, 2 * 11520>>>(nullptr, nullptr, nullptr, nullptr, out);
    tk<4, 2><<<dim3(3, 864, 2), 192, 2 * 11520>>>(nullptr, nullptr, nullptr, nullptr, out + OUT1N);
}